// round 10
// baseline (speedup 1.0000x reference)
#include <cuda_runtime.h>
#include <cuda_bf16.h>
#include <math.h>
#include <stdint.h>

// Problem constants
#define B_ 8
#define C_ 512
#define N_ 2048
#define P_ 256

typedef unsigned long long ull;

// ---------------- scratch ----------------
__device__ __nv_bfloat16 d_xs  [(size_t)B_ * N_ * 2 * C_];  // x^T split [b][n][hi(C)|lo(C)]
__device__ __nv_bfloat16 d_Wtp [(2 * P_) * 2 * C_];         // rows: th(0..255), ph(256..511)
__device__ __nv_bfloat16 d_WgS [P_ * 2 * C_];
__device__ __nv_bfloat16 d_WzS [C_ * 2 * P_];
__device__ __nv_bfloat16 d_tp  [(size_t)B_ * N_ * 4 * P_];  // [b][n][hi(2P)|lo(2P)]
__device__ __nv_bfloat16 d_gS  [(size_t)B_ * P_ * 2 * N_];  // g^T [b][p][hi(N)|lo(N)]
__device__ int8_t        d_qth [(size_t)B_ * N_ * 2 * P_];  // theta int8 [q1(256)|q2(256)]
__device__ int8_t        d_qph [(size_t)B_ * N_ * 2 * P_];  // phi   int8
__device__ float         d_sth [(size_t)B_ * N_];           // theta row scales
__device__ float         d_sph [(size_t)B_ * N_];           // phi row scales
__device__ __nv_bfloat16 d_E   [(size_t)B_ * N_ * 2 * N_];  // exp(S-64) split
__device__ float d_lpar[(size_t)B_ * N_ * 16];              // per-jtile row sums
__device__ __nv_bfloat16 d_OS  [(size_t)B_ * N_ * 2 * P_];
__device__ float d_zp[(size_t)C_ * B_ * N_];                // z channel-major [C][B*N]
__device__ ull  d_bnsum [C_];
__device__ ull  d_bnsum2[C_];
__device__ float d_scale[C_];
__device__ float d_shift[C_];

#define SC1 4194304.0   // 2^22 for sum(z)
#define SC2 65536.0     // 2^16 for sum(z^2)

// ---------------- helpers ----------------
__device__ __forceinline__ uint32_t smem_to_u32(const void* p) {
    uint32_t a;
    asm("{ .reg .u64 t; cvta.to.shared.u64 t, %1; cvt.u32.u64 %0, t; }" : "=r"(a) : "l"(p));
    return a;
}
__device__ __forceinline__ void split2(float v, __nv_bfloat16& h, __nv_bfloat16& l) {
    h = __float2bfloat16(v);
    l = __float2bfloat16(v - __bfloat162float(h));
}
__device__ __forceinline__ uint32_t packsplit_hi(float a, float b, uint32_t& lo) {
    __nv_bfloat16 h0, l0, h1, l1;
    split2(a, h0, l0); split2(b, h1, l1);
    lo = (uint32_t)__bfloat16_as_ushort(l0) | ((uint32_t)__bfloat16_as_ushort(l1) << 16);
    return (uint32_t)__bfloat16_as_ushort(h0) | ((uint32_t)__bfloat16_as_ushort(h1) << 16);
}

// ---------------- weight splits (one launch) ----------------
__global__ void split_all_kernel(const float* __restrict__ Wth, const float* __restrict__ Wph,
                                 const float* __restrict__ Wg,  const float* __restrict__ Wz,
                                 __nv_bfloat16* __restrict__ Wtp,
                                 __nv_bfloat16* __restrict__ WgS, __nv_bfloat16* __restrict__ WzS)
{
    const int which = blockIdx.y;
    const int idx = blockIdx.x * blockDim.x + threadIdx.x;
    if (idx >= P_ * C_) return;
    const float* in;
    __nv_bfloat16* out;
    int K, rofs = 0;
    if      (which == 0) { in = Wth; out = Wtp; K = C_; }
    else if (which == 1) { in = Wph; out = Wtp; K = C_; rofs = P_; }
    else if (which == 2) { in = Wg;  out = WgS; K = C_; }
    else                 { in = Wz;  out = WzS; K = P_;
                           if (idx < C_) { d_bnsum[idx] = 0ull; d_bnsum2[idx] = 0ull; } }
    int r = idx / K, k = idx % K;
    __nv_bfloat16 h, l;
    split2(in[idx], h, l);
    __nv_bfloat16* o = out + (size_t)(r + rofs) * (2 * K);
    o[k] = h;
    o[K + k] = l;
}

// ---------------- x transpose + split ----------------
__global__ void xsplit_kernel(const float* __restrict__ x,
                              __nv_bfloat16* __restrict__ xs)
{
    __shared__ float t[32][33];
    const int b = blockIdx.z;
    const int n0 = blockIdx.x * 32, c0 = blockIdx.y * 32;
    const int tx = threadIdx.x, ty = threadIdx.y;
    const float* xb = x + (size_t)b * C_ * N_;
    t[ty][tx] = xb[(size_t)(c0 + ty) * N_ + n0 + tx];
    __syncthreads();
    float v = t[tx][ty];
    int n = n0 + ty, c = c0 + tx;
    __nv_bfloat16 h, l;
    split2(v, h, l);
    size_t row = ((size_t)b * N_ + n) * (size_t)(2 * C_);
    xs[row + c] = h;
    xs[row + C_ + c] = l;
}

// ---------------- quantize theta/phi rows to 2-limb int8 + fp32 scale ----------------
// tp row layout: [hi(0:512) | lo(512:1024)]; theta cols 0..255, phi cols 256..511.
__global__ void quant_kernel(const __nv_bfloat16* __restrict__ tp,
                             int8_t* __restrict__ qth, int8_t* __restrict__ qph,
                             float* __restrict__ sth, float* __restrict__ sph)
{
    const int wid  = threadIdx.x >> 5;
    const int lane = threadIdx.x & 31;
    const int n = blockIdx.x * 8 + wid;
    const int b = blockIdx.z;
    const int which = blockIdx.y;        // 0 theta, 1 phi
    const __nv_bfloat16* rowp = tp + ((size_t)b * N_ + n) * 1024 + which * 256;

    // read 8 values: hi + lo
    float v[8];
    {
        uint4 hv = *(const uint4*)(rowp + lane * 8);
        uint4 lv = *(const uint4*)(rowp + 512 + lane * 8);
        const ushort* hp = (const ushort*)&hv;
        const ushort* lp2 = (const ushort*)&lv;
#pragma unroll
        for (int i = 0; i < 8; i++)
            v[i] = __bfloat162float(__ushort_as_bfloat16(hp[i])) +
                   __bfloat162float(__ushort_as_bfloat16(lp2[i]));
    }
    float m = 0.f;
#pragma unroll
    for (int i = 0; i < 8; i++) m = fmaxf(m, fabsf(v[i]));
#pragma unroll
    for (int s = 16; s > 0; s >>= 1)
        m = fmaxf(m, __shfl_xor_sync(0xFFFFFFFFu, m, s));

    const float scale = fmaxf(m, 1e-20f) * (1.0f / 0.992f);
    const float inv128 = 128.0f / scale;

    uint32_t p1[2], p2[2];
    char* c1 = (char*)p1;
    char* c2 = (char*)p2;
#pragma unroll
    for (int i = 0; i < 8; i++) {
        float r128 = v[i] * inv128;          // |r128| <= 126.98
        float q1 = rintf(r128);
        float e  = (r128 - q1) * 256.0f;     // in [-128, 128]
        float q2 = rintf(e);
        q2 = fminf(fmaxf(q2, -127.0f), 127.0f);
        c1[i] = (char)(int)q1;
        c2[i] = (char)(int)q2;
    }
    int8_t* orow = (which ? qph : qth) + ((size_t)b * N_ + n) * 512;
    *(uint2*)(orow + lane * 8)       = make_uint2(p1[0], p1[1]);
    *(uint2*)(orow + 256 + lane * 8) = make_uint2(p2[0], p2[1]);
    if (lane == 0) (which ? sph : sth)[(size_t)b * N_ + n] = scale;
}

// ---------------- bf16 split-3 GEMM (modes 1,3,4) ----------------
#define CH 64
#define PAD 72
#define STG_ELEMS (128 * PAD)
#define GEMM_SMEM (6 * STG_ELEMS * 2)

#define LDSM4(d, addr) \
    asm volatile("ldmatrix.sync.aligned.m8n8.x4.shared.b16 {%0,%1,%2,%3}, [%4];" \
        : "=r"((d)[0]), "=r"((d)[1]), "=r"((d)[2]), "=r"((d)[3]) : "r"(addr))

#define MMA16816(ac, a, b0, b1) \
    asm volatile("mma.sync.aligned.m16n8k16.row.col.f32.bf16.bf16.f32 " \
        "{%0,%1,%2,%3}, {%4,%5,%6,%7}, {%8,%9}, {%0,%1,%2,%3};" \
        : "+f"((ac)[0]), "+f"((ac)[1]), "+f"((ac)[2]), "+f"((ac)[3]) \
        : "r"((a)[0]), "r"((a)[1]), "r"((a)[2]), "r"((a)[3]), "r"(b0), "r"(b1))

#define IMMA16832(ac, a, b0, b1) \
    asm volatile("mma.sync.aligned.m16n8k32.row.col.s32.s8.s8.s32 " \
        "{%0,%1,%2,%3}, {%4,%5,%6,%7}, {%8,%9}, {%0,%1,%2,%3};" \
        : "+r"((ac)[0]), "+r"((ac)[1]), "+r"((ac)[2]), "+r"((ac)[3]) \
        : "r"((a)[0]), "r"((a)[1]), "r"((a)[2]), "r"((a)[3]), "r"(b0), "r"(b1))

__global__ void __launch_bounds__(256, 2) gemm_mma_kernel(
    const __nv_bfloat16* __restrict__ A, int lda, int hlA,
    const __nv_bfloat16* __restrict__ Bp, int ldb, int hlB,
    void* __restrict__ Cout, int ldc, int K, int mode, int J,
    size_t sA, size_t sB, size_t sC, float* __restrict__ laux)
{
    extern __shared__ __nv_bfloat16 sm[];
    __shared__ ull  s_ch[256];
    __shared__ float s_lrow[128];
    const uint32_t smu = smem_to_u32(sm);

    const int tid  = threadIdx.x;
    const int wid  = tid >> 5;
    const int lane = tid & 31;
    const int wm = wid & 3;
    const int wn = wid >> 2;
    const int bz = blockIdx.z;
    A  += (size_t)bz * sA;
    Bp += (size_t)bz * sB;
    const int m0 = blockIdx.y * 128;
    const int j0 = blockIdx.x * 128;

    if (mode == 3 && tid < 128) {
        const float* p = laux + ((size_t)bz * N_ + m0 + tid) * 16;
        float s = 0.f;
#pragma unroll
        for (int j = 0; j < 16; j++) s += p[j];
        s_lrow[tid] = 1.f / s;
    }
    if (mode == 4 && tid < 256) s_ch[tid] = 0ull;

    float acc[2][8][4];
#pragma unroll
    for (int mt = 0; mt < 2; mt++)
#pragma unroll
        for (int nb = 0; nb < 8; nb++)
#pragma unroll
            for (int q = 0; q < 4; q++) acc[mt][nb][q] = 0.f;

    const int KC = K / CH;
    const int NC = 3 * KC;

    auto issue_chunk = [&](int aOff, int bOff, int buf) {
        const uint32_t aBase = smu + (uint32_t)(2 * buf) * STG_ELEMS * 2;
        const uint32_t bBase = smu + (uint32_t)(2 * buf + 1) * STG_ELEMS * 2;
#pragma unroll
        for (int i = 0; i < 4; i++) {
            int lin = tid + i * 256;
            int r  = lin >> 3;
            int c8 = lin & 7;
            const __nv_bfloat16* gA = A  + (size_t)(m0 + r) * lda + aOff + c8 * 8;
            const __nv_bfloat16* gB = Bp + (size_t)(j0 + r) * ldb + bOff + c8 * 8;
            uint32_t sa = aBase + (uint32_t)(r * PAD + c8 * 8) * 2;
            uint32_t sb = bBase + (uint32_t)(r * PAD + c8 * 8) * 2;
            asm volatile("cp.async.cg.shared.global [%0], [%1], 16;" :: "r"(sa), "l"(gA));
            asm volatile("cp.async.cg.shared.global [%0], [%1], 16;" :: "r"(sb), "l"(gB));
        }
        asm volatile("cp.async.commit_group;" ::: "memory");
    };

    issue_chunk(0, 0, 0);
    issue_chunk(CH, CH, 1);

    int pf_t = 0, pf_off = 2 * CH;
    if (pf_off >= K) { pf_off -= K; pf_t++; }

    const int lrow = lane & 15;
    const int kun  = lane >> 4;
    const uint32_t aRowOff = (uint32_t)((wm * 32 + lrow) * PAD + kun * 8) * 2;
    const uint32_t bRowOff = (uint32_t)((wn * 64 + lrow) * PAD + kun * 8) * 2;

    int buf = 0;
    for (int c = 0; c < NC; c++) {
        if (c + 1 < NC) asm volatile("cp.async.wait_group 1;" ::: "memory");
        else            asm volatile("cp.async.wait_group 0;" ::: "memory");
        __syncthreads();
        if (c + 2 < NC) {
            int aOff = pf_off + ((pf_t == 2) ? hlA : 0);
            int bOff = pf_off + ((pf_t == 1) ? hlB : 0);
            issue_chunk(aOff, bOff, (buf + 2) % 3);
            pf_off += CH;
            if (pf_off == K) { pf_off = 0; pf_t++; }
        }

        const uint32_t aBase = smu + (uint32_t)(2 * buf) * STG_ELEMS * 2 + aRowOff;
        const uint32_t bBase = smu + (uint32_t)(2 * buf + 1) * STG_ELEMS * 2 + bRowOff;

        uint32_t af[2][2][4];
        uint32_t bg[2][4];

        LDSM4(af[0][0], aBase);
        LDSM4(af[0][1], aBase + 16 * PAD * 2);

#pragma unroll
        for (int ks = 0; ks < 4; ks++) {
            const int cur = ks & 1, nxt = cur ^ 1;
            const uint32_t kOff = (uint32_t)(ks * 32);
            LDSM4(bg[0], bBase + kOff);
#pragma unroll
            for (int nb2 = 0; nb2 < 4; nb2++) {
                const int gc = nb2 & 1, gn = gc ^ 1;
                if (nb2 < 3) {
                    LDSM4(bg[gn], bBase + kOff + (uint32_t)((nb2 + 1) * 16 * PAD * 2));
                } else if (ks < 3) {
                    LDSM4(af[nxt][0], aBase + kOff + 32);
                    LDSM4(af[nxt][1], aBase + kOff + 32 + 16 * PAD * 2);
                }
#pragma unroll
                for (int mt = 0; mt < 2; mt++) {
                    MMA16816(acc[mt][nb2 * 2],     af[cur][mt], bg[gc][0], bg[gc][2]);
                    MMA16816(acc[mt][nb2 * 2 + 1], af[cur][mt], bg[gc][1], bg[gc][3]);
                }
            }
        }
        buf = (buf + 1) % 3;
    }

    // ---------------- epilogue ----------------
    const int g = lane >> 2;
    const int t = lane & 3;

#pragma unroll
    for (int mt = 0; mt < 2; mt++) {
        const int row0 = m0 + wm * 32 + mt * 16 + g;
        const int row1 = row0 + 8;
        float rs0 = 0.f, rs1 = 0.f, rq0 = 0.f, rq1 = 0.f;
#pragma unroll
        for (int nb = 0; nb < 8; nb++) {
            const int col = j0 + wn * 64 + nb * 8 + t * 2;
            float d0 = acc[mt][nb][0], d1 = acc[mt][nb][1];
            float d2 = acc[mt][nb][2], d3 = acc[mt][nb][3];
            if (mode == 4) {
                float* base = (float*)Cout + (size_t)bz * sC;
                *(float2*)(base + (size_t)row0 * ldc + col) = make_float2(d0, d1);
                *(float2*)(base + (size_t)row1 * ldc + col) = make_float2(d2, d3);
                rs0 += d0 + d1; rs1 += d2 + d3;
                rq0 += d0 * d0 + d1 * d1; rq1 += d2 * d2 + d3 * d3;
            } else {
                if (mode == 3) {
                    float inv0 = s_lrow[row0 - m0];
                    float inv1 = s_lrow[row1 - m0];
                    d0 *= inv0; d1 *= inv0; d2 *= inv1; d3 *= inv1;
                }
                __nv_bfloat16* base = (__nv_bfloat16*)Cout + (size_t)bz * sC;
                uint32_t lp0, lp1;
                uint32_t hp0 = packsplit_hi(d0, d1, lp0);
                uint32_t hp1 = packsplit_hi(d2, d3, lp1);
                __nv_bfloat16* r0p = base + (size_t)row0 * ldc + col;
                __nv_bfloat16* r1p = base + (size_t)row1 * ldc + col;
                *(uint32_t*)(r0p)     = hp0;
                *(uint32_t*)(r0p + J) = lp0;
                *(uint32_t*)(r1p)     = hp1;
                *(uint32_t*)(r1p + J) = lp1;
            }
        }
        if (mode == 4) {
            rs0 += __shfl_xor_sync(0xFFFFFFFFu, rs0, 1);
            rs0 += __shfl_xor_sync(0xFFFFFFFFu, rs0, 2);
            rs1 += __shfl_xor_sync(0xFFFFFFFFu, rs1, 1);
            rs1 += __shfl_xor_sync(0xFFFFFFFFu, rs1, 2);
            rq0 += __shfl_xor_sync(0xFFFFFFFFu, rq0, 1);
            rq0 += __shfl_xor_sync(0xFFFFFFFFu, rq0, 2);
            rq1 += __shfl_xor_sync(0xFFFFFFFFu, rq1, 1);
            rq1 += __shfl_xor_sync(0xFFFFFFFFu, rq1, 2);
            if (t == 0) {
                int r0 = wm * 32 + mt * 16 + g, r1 = r0 + 8;
                atomicAdd(&s_ch[r0], (ull)(long long)llrintf(rs0 * (float)SC1));
                atomicAdd(&s_ch[r1], (ull)(long long)llrintf(rs1 * (float)SC1));
                atomicAdd(&s_ch[128 + r0], (ull)(long long)llrintf(rq0 * (float)SC2));
                atomicAdd(&s_ch[128 + r1], (ull)(long long)llrintf(rq1 * (float)SC2));
            }
        }
    }

    if (mode == 4) {
        __syncthreads();
        if (tid < 128) {
            atomicAdd(&d_bnsum [m0 + tid], s_ch[tid]);
            atomicAdd(&d_bnsum2[m0 + tid], s_ch[128 + tid]);
        }
    }
}

// ---------------- int8 scores GEMM: E = exp(S-64) + row partial sums ----------------
// A = qth [b][n][q1(256)|q2(256)], B = qph. K=256 per limb.
// Chunk plan (128 int8 per chunk): c0,c1 = q1*q1 ; <<8 ; c2..c5 = cross terms.
// S = s_th[n]*s_ph[m]*2^-22*acc.
__global__ void __launch_bounds__(256, 2) scores_i8_kernel(
    const int8_t* __restrict__ A, const int8_t* __restrict__ Bp,
    __nv_bfloat16* __restrict__ Eout,
    const float* __restrict__ sthp, const float* __restrict__ sphp,
    float* __restrict__ laux)
{
    extern __shared__ __nv_bfloat16 sm[];
    __shared__ float s_th[128];
    __shared__ float s_ph[128];
    const uint32_t smu = smem_to_u32(sm);

    const int tid  = threadIdx.x;
    const int wid  = tid >> 5;
    const int lane = tid & 31;
    const int wm = wid & 3;
    const int wn = wid >> 2;
    const int bz = blockIdx.z;
    const int m0 = blockIdx.y * 128;
    const int j0 = blockIdx.x * 128;

    A  += (size_t)bz * N_ * 512;
    Bp += (size_t)bz * N_ * 512;

    if (tid < 128) {
        s_th[tid] = sthp[(size_t)bz * N_ + m0 + tid];
        s_ph[tid] = sphp[(size_t)bz * N_ + j0 + tid];
    }

    int acc[2][8][4];
#pragma unroll
    for (int mt = 0; mt < 2; mt++)
#pragma unroll
        for (int nb = 0; nb < 8; nb++)
#pragma unroll
            for (int q = 0; q < 4; q++) acc[mt][nb][q] = 0;

    // chunk offset tables (int8 units)
    const int aOffs[6] = {0, 128, 0, 128, 256, 384};
    const int bOffs[6] = {0, 128, 256, 384, 0, 128};

    auto issue_chunk = [&](int ci, int buf) {
        const int aOff = aOffs[ci], bOff = bOffs[ci];
        const uint32_t aBase = smu + (uint32_t)(2 * buf) * STG_ELEMS * 2;
        const uint32_t bBase = smu + (uint32_t)(2 * buf + 1) * STG_ELEMS * 2;
#pragma unroll
        for (int i = 0; i < 4; i++) {
            int lin = tid + i * 256;
            int r  = lin >> 3;
            int c8 = lin & 7;
            const int8_t* gA = A  + (size_t)(m0 + r) * 512 + aOff + c8 * 16;
            const int8_t* gB = Bp + (size_t)(j0 + r) * 512 + bOff + c8 * 16;
            uint32_t sa = aBase + (uint32_t)(r * (PAD * 2) + c8 * 16);
            uint32_t sb = bBase + (uint32_t)(r * (PAD * 2) + c8 * 16);
            asm volatile("cp.async.cg.shared.global [%0], [%1], 16;" :: "r"(sa), "l"(gA));
            asm volatile("cp.async.cg.shared.global [%0], [%1], 16;" :: "r"(sb), "l"(gB));
        }
        asm volatile("cp.async.commit_group;" ::: "memory");
    };

    issue_chunk(0, 0);
    issue_chunk(1, 1);

    const int lrow = lane & 15;
    const int kun  = lane >> 4;
    const uint32_t aRowOff = (uint32_t)((wm * 32 + lrow) * (PAD * 2) + kun * 16);
    const uint32_t bRowOff = (uint32_t)((wn * 64 + lrow) * (PAD * 2) + kun * 16);

    int buf = 0;
    for (int c = 0; c < 6; c++) {
        if (c + 1 < 6) asm volatile("cp.async.wait_group 1;" ::: "memory");
        else           asm volatile("cp.async.wait_group 0;" ::: "memory");
        __syncthreads();
        if (c + 2 < 6) issue_chunk(c + 2, (buf + 2) % 3);

        if (c == 2) {   // after q1q1 chunks: scale up exactly by 2^8
#pragma unroll
            for (int mt = 0; mt < 2; mt++)
#pragma unroll
                for (int nb = 0; nb < 8; nb++)
#pragma unroll
                    for (int q = 0; q < 4; q++) acc[mt][nb][q] <<= 8;
        }

        const uint32_t aBase = smu + (uint32_t)(2 * buf) * STG_ELEMS * 2 + aRowOff;
        const uint32_t bBase = smu + (uint32_t)(2 * buf + 1) * STG_ELEMS * 2 + bRowOff;

        uint32_t af[2][2][4];
        uint32_t bg[2][4];

        LDSM4(af[0][0], aBase);
        LDSM4(af[0][1], aBase + 16 * PAD * 2);

#pragma unroll
        for (int ks = 0; ks < 4; ks++) {
            const int cur = ks & 1, nxt = cur ^ 1;
            const uint32_t kOff = (uint32_t)(ks * 32);
            LDSM4(bg[0], bBase + kOff);
#pragma unroll
            for (int nb2 = 0; nb2 < 4; nb2++) {
                const int gc = nb2 & 1, gn = gc ^ 1;
                if (nb2 < 3) {
                    LDSM4(bg[gn], bBase + kOff + (uint32_t)((nb2 + 1) * 16 * PAD * 2));
                } else if (ks < 3) {
                    LDSM4(af[nxt][0], aBase + kOff + 32);
                    LDSM4(af[nxt][1], aBase + kOff + 32 + 16 * PAD * 2);
                }
#pragma unroll
                for (int mt = 0; mt < 2; mt++) {
                    IMMA16832(acc[mt][nb2 * 2],     af[cur][mt], bg[gc][0], bg[gc][2]);
                    IMMA16832(acc[mt][nb2 * 2 + 1], af[cur][mt], bg[gc][1], bg[gc][3]);
                }
            }
        }
        buf = (buf + 1) % 3;
    }

    // ---------------- epilogue: S -> exp(S-64), split write, row sums ----------------
    const int g = lane >> 2;
    const int t = lane & 3;
    float* lsm = (float*)sm;

    __syncthreads();
    if (tid < 128) lsm[tid] = 0.f;
    __syncthreads();

    const float SFX = 1.0f / 4194304.0f;    // 2^-22

#pragma unroll
    for (int mt = 0; mt < 2; mt++) {
        const int row0 = m0 + wm * 32 + mt * 16 + g;
        const int row1 = row0 + 8;
        const float st0 = s_th[row0 - m0] * SFX;
        const float st1 = s_th[row1 - m0] * SFX;
        float rs0 = 0.f, rs1 = 0.f;
#pragma unroll
        for (int nb = 0; nb < 8; nb++) {
            const int col = j0 + wn * 64 + nb * 8 + t * 2;
            const float sp0 = s_ph[col - j0];
            const float sp1 = s_ph[col + 1 - j0];
            float d0 = (float)acc[mt][nb][0] * st0 * sp0;
            float d1 = (float)acc[mt][nb][1] * st0 * sp1;
            float d2 = (float)acc[mt][nb][2] * st1 * sp0;
            float d3 = (float)acc[mt][nb][3] * st1 * sp1;
            d0 = expf(d0 - 64.f); d1 = expf(d1 - 64.f);
            d2 = expf(d2 - 64.f); d3 = expf(d3 - 64.f);
            rs0 += d0 + d1;
            rs1 += d2 + d3;
            uint32_t lp0, lp1;
            uint32_t hp0 = packsplit_hi(d0, d1, lp0);
            uint32_t hp1 = packsplit_hi(d2, d3, lp1);
            __nv_bfloat16* base = Eout + (size_t)bz * N_ * 2 * N_;
            __nv_bfloat16* r0p = base + (size_t)row0 * (2 * N_) + col;
            __nv_bfloat16* r1p = base + (size_t)row1 * (2 * N_) + col;
            *(uint32_t*)(r0p)      = hp0;
            *(uint32_t*)(r0p + N_) = lp0;
            *(uint32_t*)(r1p)      = hp1;
            *(uint32_t*)(r1p + N_) = lp1;
        }
        rs0 += __shfl_xor_sync(0xFFFFFFFFu, rs0, 1);
        rs0 += __shfl_xor_sync(0xFFFFFFFFu, rs0, 2);
        rs1 += __shfl_xor_sync(0xFFFFFFFFu, rs1, 1);
        rs1 += __shfl_xor_sync(0xFFFFFFFFu, rs1, 2);
        if (t == 0) {
            atomicAdd(&lsm[wm * 32 + mt * 16 + g], rs0);
            atomicAdd(&lsm[wm * 32 + mt * 16 + g + 8], rs1);
        }
    }

    __syncthreads();
    if (tid < 128)
        laux[((size_t)bz * N_ + m0 + tid) * 16 + blockIdx.x] = lsm[tid];
}

// ---------------- BN scale/shift from fixed-point sums ----------------
__global__ void bn_stats2_kernel(const float* __restrict__ gamma,
                                 const float* __restrict__ beta,
                                 float* __restrict__ scale,
                                 float* __restrict__ shift)
{
    int c = blockIdx.x * blockDim.x + threadIdx.x;
    if (c >= C_) return;
    const double M = (double)(B_ * N_);
    double mean = (double)(long long)d_bnsum[c]  / SC1 / M;
    double ms   = (double)(long long)d_bnsum2[c] / SC2 / M;
    double var  = ms - mean * mean;
    double inv  = 1.0 / sqrt(var + 1e-5);
    double sc   = (double)gamma[c] * inv;
    scale[c] = (float)sc;
    shift[c] = (float)((double)beta[c] - mean * sc);
}

// ---------------- finalize ----------------
__global__ void finalize_kernel(const float* __restrict__ zp,
                                const float* __restrict__ x,
                                const float* __restrict__ scale,
                                const float* __restrict__ shift,
                                float* __restrict__ out)
{
    const size_t idx4 = (size_t)blockIdx.x * blockDim.x + threadIdx.x;
    const size_t total4 = (size_t)B_ * C_ * N_ / 4;
    if (idx4 >= total4) return;
    const int nq = N_ / 4;
    int n4 = (int)(idx4 % nq);
    int c  = (int)((idx4 / nq) % C_);
    int b  = (int)(idx4 / ((size_t)nq * C_));

    float4 z = ((const float4*)zp)[(size_t)c * (B_ * N_ / 4) + (size_t)b * nq + n4];
    float4 xv = ((const float4*)x)[idx4];
    const float sc = scale[c], sh = shift[c];
    float4 o;
    o.x = z.x * sc + sh + xv.x;
    o.y = z.y * sc + sh + xv.y;
    o.z = z.z * sc + sh + xv.z;
    o.w = z.w * sc + sh + xv.w;
    ((float4*)out)[idx4] = o;
}

// ---------------- launch ----------------
template <typename T>
static T* sym_addr(const void* sym)
{
    void* p = nullptr;
    cudaGetSymbolAddress(&p, sym);
    return (T*)p;
}

extern "C" void kernel_launch(void* const* d_in, const int* in_sizes, int n_in,
                              void* d_out, int out_size)
{
    const float* x     = (const float*)d_in[0];
    const float* Wg    = (const float*)d_in[1];
    const float* Wth   = (const float*)d_in[2];
    const float* Wph   = (const float*)d_in[3];
    const float* Wz    = (const float*)d_in[4];
    const float* gamma = (const float*)d_in[5];
    const float* beta  = (const float*)d_in[6];
    float* out = (float*)d_out;

    __nv_bfloat16* xs  = sym_addr<__nv_bfloat16>(d_xs);
    __nv_bfloat16* Wtp = sym_addr<__nv_bfloat16>(d_Wtp);
    __nv_bfloat16* WgS = sym_addr<__nv_bfloat16>(d_WgS);
    __nv_bfloat16* WzS = sym_addr<__nv_bfloat16>(d_WzS);
    __nv_bfloat16* tp  = sym_addr<__nv_bfloat16>(d_tp);
    __nv_bfloat16* gS  = sym_addr<__nv_bfloat16>(d_gS);
    int8_t*        qth = sym_addr<int8_t>(d_qth);
    int8_t*        qph = sym_addr<int8_t>(d_qph);
    float*         sth = sym_addr<float>(d_sth);
    float*         sph = sym_addr<float>(d_sph);
    __nv_bfloat16* E   = sym_addr<__nv_bfloat16>(d_E);
    float*         lp  = sym_addr<float>(d_lpar);
    __nv_bfloat16* OS  = sym_addr<__nv_bfloat16>(d_OS);
    float* zp    = sym_addr<float>(d_zp);
    float* scale = sym_addr<float>(d_scale);
    float* shift = sym_addr<float>(d_shift);

    cudaFuncSetAttribute(gemm_mma_kernel,
                         cudaFuncAttributeMaxDynamicSharedMemorySize, GEMM_SMEM);
    cudaFuncSetAttribute(scores_i8_kernel,
                         cudaFuncAttributeMaxDynamicSharedMemorySize, GEMM_SMEM);

    // 1) weight splits + zero bn accumulators
    split_all_kernel<<<dim3((P_ * C_ + 255) / 256, 4), 256>>>(
        Wth, Wph, Wg, Wz, Wtp, WgS, WzS);
    // 2) x transpose + split
    xsplit_kernel<<<dim3(N_ / 32, C_ / 32, B_), dim3(32, 32)>>>(x, xs);
    // 3) theta+phi merged: tp [b][n][hi(2P)|lo(2P)]
    gemm_mma_kernel<<<dim3((2 * P_) / 128, N_ / 128, B_), 256, GEMM_SMEM>>>(
        xs, 2 * C_, C_, Wtp, 2 * C_, C_, tp, 4 * P_, C_, 1, 2 * P_,
        (size_t)N_ * 2 * C_, 0, (size_t)N_ * 4 * P_, nullptr);
    // 4) g^T [b][p][hi(N)|lo(N)]
    gemm_mma_kernel<<<dim3(N_ / 128, P_ / 128, B_), 256, GEMM_SMEM>>>(
        WgS, 2 * C_, C_, xs, 2 * C_, C_, gS, 2 * N_, C_, 1, N_,
        0, (size_t)N_ * 2 * C_, (size_t)P_ * 2 * N_, nullptr);
    // 5) quantize theta/phi to 2-limb int8
    quant_kernel<<<dim3(N_ / 8, 2, B_), 256>>>(tp, qth, qph, sth, sph);
    // 6) int8 scores -> E = exp(S-64) + row partial sums  <-- ncu lands here
    scores_i8_kernel<<<dim3(N_ / 128, N_ / 128, B_), 256, GEMM_SMEM>>>(
        qth, qph, E, sth, sph, lp);
    // 7) PV: O = (E x g) / l
    gemm_mma_kernel<<<dim3(P_ / 128, N_ / 128, B_), 256, GEMM_SMEM>>>(
        E, 2 * N_, N_, gS, 2 * N_, N_, OS, 2 * P_, N_, 3, P_,
        (size_t)N_ * 2 * N_, (size_t)P_ * 2 * N_, (size_t)N_ * 2 * P_, lp);
    // 8) z fp32 [C][B*N] + fused BN channel sums
    gemm_mma_kernel<<<dim3((B_ * N_) / 128, C_ / 128, 1), 256, GEMM_SMEM>>>(
        WzS, 2 * P_, P_, OS, 2 * P_, P_, zp, B_ * N_, P_, 4, 0,
        0, 0, 0, nullptr);
    // 9) BN scale/shift
    bn_stats2_kernel<<<2, 256>>>(gamma, beta, scale, shift);
    // 10) finalize
    {
        const int total4 = B_ * C_ * N_ / 4;
        finalize_kernel<<<(total4 + 255) / 256, 256>>>(zp, x, scale, shift, out);
    }
}

// round 12
// speedup vs baseline: 1.3409x; 1.3409x over previous
#include <cuda_runtime.h>
#include <cuda_bf16.h>
#include <cuda_fp16.h>
#include <math.h>
#include <stdint.h>

// Problem constants
#define B_ 8
#define C_ 512
#define N_ 2048
#define P_ 256

typedef unsigned long long ull;

// ---------------- scratch ----------------
// fp16 limb buffers
__device__ __half d_xs [(size_t)B_ * N_ * 2 * C_];  // x^T split [b][n][hi(C)|lo(C)]
__device__ __half d_Wtp[(2 * P_) * 2 * C_];         // rows: th(0..255), ph(256..511)
__device__ __half d_WgS[P_ * 2 * C_];
__device__ __half d_WzS[C_ * 2 * P_];
__device__ __half d_tp [(size_t)B_ * N_ * 4 * P_];  // [b][n][hi(2P)|lo(2P)]
__device__ __half d_OS [(size_t)B_ * N_ * 2 * P_];
// bf16 buffers (E needs bf16 range; gS must match E's type in PV)
__device__ __nv_bfloat16 d_gS[(size_t)B_ * P_ * 2 * N_]; // g^T [b][p][hi(N)|lo(N)]
__device__ __nv_bfloat16 d_E [(size_t)B_ * N_ * 2 * N_]; // exp(S-64) split
__device__ float d_lpar[(size_t)B_ * N_ * 16];           // per-jtile row sums
__device__ float d_zp[(size_t)C_ * B_ * N_];             // z channel-major [C][B*N]
__device__ ull  d_bnsum [C_];
__device__ ull  d_bnsum2[C_];
__device__ float d_scale[C_];
__device__ float d_shift[C_];

#define SC1 4194304.0   // 2^22 for sum(z)
#define SC2 65536.0     // 2^16 for sum(z^2)

// ---------------- helpers ----------------
__device__ __forceinline__ uint32_t smem_to_u32(const void* p) {
    uint32_t a;
    asm("{ .reg .u64 t; cvta.to.shared.u64 t, %1; cvt.u32.u64 %0, t; }" : "=r"(a) : "l"(p));
    return a;
}
__device__ __forceinline__ void split2h(float v, __half& h, __half& l) {
    h = __float2half(v);
    l = __float2half(v - __half2float(h));
}
// pack split pair; FO=1 -> fp16 limbs, FO=0 -> bf16 limbs
template <int FO>
__device__ __forceinline__ uint32_t packsplit2(float a, float b, uint32_t& lo) {
    if (FO) {
        __half h0, l0, h1, l1;
        split2h(a, h0, l0); split2h(b, h1, l1);
        lo = (uint32_t)__half_as_ushort(l0) | ((uint32_t)__half_as_ushort(l1) << 16);
        return (uint32_t)__half_as_ushort(h0) | ((uint32_t)__half_as_ushort(h1) << 16);
    } else {
        __nv_bfloat16 h0 = __float2bfloat16(a);
        __nv_bfloat16 l0 = __float2bfloat16(a - __bfloat162float(h0));
        __nv_bfloat16 h1 = __float2bfloat16(b);
        __nv_bfloat16 l1 = __float2bfloat16(b - __bfloat162float(h1));
        lo = (uint32_t)__bfloat16_as_ushort(l0) | ((uint32_t)__bfloat16_as_ushort(l1) << 16);
        return (uint32_t)__bfloat16_as_ushort(h0) | ((uint32_t)__bfloat16_as_ushort(h1) << 16);
    }
}

// ---------------- weight splits (one launch) ----------------
__global__ void split_all_kernel(const float* __restrict__ Wth, const float* __restrict__ Wph,
                                 const float* __restrict__ Wg,  const float* __restrict__ Wz,
                                 __half* __restrict__ Wtp,
                                 __half* __restrict__ WgS, __half* __restrict__ WzS)
{
    const int which = blockIdx.y;
    const int idx = blockIdx.x * blockDim.x + threadIdx.x;
    if (idx >= P_ * C_) return;
    const float* in;
    __half* out;
    int K, rofs = 0;
    if      (which == 0) { in = Wth; out = Wtp; K = C_; }
    else if (which == 1) { in = Wph; out = Wtp; K = C_; rofs = P_; }
    else if (which == 2) { in = Wg;  out = WgS; K = C_; }
    else                 { in = Wz;  out = WzS; K = P_;
                           if (idx < C_) { d_bnsum[idx] = 0ull; d_bnsum2[idx] = 0ull; } }
    int r = idx / K, k = idx % K;
    __half h, l;
    split2h(in[idx], h, l);
    __half* o = out + (size_t)(r + rofs) * (2 * K);
    o[k] = h;
    o[K + k] = l;
}

// ---------------- x transpose + split (fp16) ----------------
__global__ void xsplit_kernel(const float* __restrict__ x,
                              __half* __restrict__ xs)
{
    __shared__ float t[32][33];
    const int b = blockIdx.z;
    const int n0 = blockIdx.x * 32, c0 = blockIdx.y * 32;
    const int tx = threadIdx.x, ty = threadIdx.y;
    const float* xb = x + (size_t)b * C_ * N_;
    t[ty][tx] = xb[(size_t)(c0 + ty) * N_ + n0 + tx];
    __syncthreads();
    float v = t[tx][ty];
    int n = n0 + ty, c = c0 + tx;
    __half h, l;
    split2h(v, h, l);
    size_t row = ((size_t)b * N_ + n) * (size_t)(2 * C_);
    xs[row + c] = h;
    xs[row + C_ + c] = l;
}

// ---------------- mma.sync split GEMM (templated on in/out limb type) ----------------
// C[i,j] = sum over nterms t of sum_k A[i, aoff(t)+k] * B[j, boff(t)+k], k in [0,K)
//   nterms=3: (hi,hi),(hi,lo),(lo,hi)     aoff = t==2?hlA:0 ; boff = t==1?hlB:0
//   nterms=2: (hi,hi),(lo,hi)             aoff = t==1?hlA:0 ; boff = 0
// FI: 1 = fp16 operands, 0 = bf16 operands. FO: limb type for split outputs.
// mode: 1 = split [hi|lo] out; 2 = exp(acc-64) split + row partial sums (laux);
//       3 = scale by 1/rowsum(laux partials), split out; 4 = fp32 out + BN channel sums.
#define CH 64
#define PAD 72
#define STG_ELEMS (128 * PAD)
#define GEMM_SMEM (6 * STG_ELEMS * 2)

#define LDSM4(d, addr) \
    asm volatile("ldmatrix.sync.aligned.m8n8.x4.shared.b16 {%0,%1,%2,%3}, [%4];" \
        : "=r"((d)[0]), "=r"((d)[1]), "=r"((d)[2]), "=r"((d)[3]) : "r"(addr))

template <int FI>
__device__ __forceinline__ void mma16816(float ac[4], const uint32_t a[4],
                                         uint32_t b0, uint32_t b1) {
    if (FI) {
        asm volatile("mma.sync.aligned.m16n8k16.row.col.f32.f16.f16.f32 "
            "{%0,%1,%2,%3}, {%4,%5,%6,%7}, {%8,%9}, {%0,%1,%2,%3};"
            : "+f"(ac[0]), "+f"(ac[1]), "+f"(ac[2]), "+f"(ac[3])
            : "r"(a[0]), "r"(a[1]), "r"(a[2]), "r"(a[3]), "r"(b0), "r"(b1));
    } else {
        asm volatile("mma.sync.aligned.m16n8k16.row.col.f32.bf16.bf16.f32 "
            "{%0,%1,%2,%3}, {%4,%5,%6,%7}, {%8,%9}, {%0,%1,%2,%3};"
            : "+f"(ac[0]), "+f"(ac[1]), "+f"(ac[2]), "+f"(ac[3])
            : "r"(a[0]), "r"(a[1]), "r"(a[2]), "r"(a[3]), "r"(b0), "r"(b1));
    }
}

template <int FI, int FO>
__global__ void __launch_bounds__(256, 2) gemm_mma_kernel(
    const uint16_t* __restrict__ A, int lda, int hlA,
    const uint16_t* __restrict__ Bp, int ldb, int hlB,
    void* __restrict__ Cout, int ldc, int K, int mode, int J, int nterms,
    size_t sA, size_t sB, size_t sC, float* __restrict__ laux)
{
    extern __shared__ uint16_t sm[];
    __shared__ ull  s_ch[256];
    __shared__ float s_lrow[128];
    const uint32_t smu = smem_to_u32(sm);

    const int tid  = threadIdx.x;
    const int wid  = tid >> 5;
    const int lane = tid & 31;
    const int wm = wid & 3;
    const int wn = wid >> 2;
    const int bz = blockIdx.z;
    A  += (size_t)bz * sA;
    Bp += (size_t)bz * sB;
    const int m0 = blockIdx.y * 128;
    const int j0 = blockIdx.x * 128;

    if (mode == 3 && tid < 128) {
        const float* p = laux + ((size_t)bz * N_ + m0 + tid) * 16;
        float s = 0.f;
#pragma unroll
        for (int j = 0; j < 16; j++) s += p[j];
        s_lrow[tid] = 1.f / s;
    }
    if (mode == 4 && tid < 256) s_ch[tid] = 0ull;

    float acc[2][8][4];
#pragma unroll
    for (int mt = 0; mt < 2; mt++)
#pragma unroll
        for (int nb = 0; nb < 8; nb++)
#pragma unroll
            for (int q = 0; q < 4; q++) acc[mt][nb][q] = 0.f;

    const int KC = K / CH;
    const int NC = nterms * KC;

    auto issue_chunk = [&](int aOff, int bOff, int buf) {
        const uint32_t aBase = smu + (uint32_t)(2 * buf) * STG_ELEMS * 2;
        const uint32_t bBase = smu + (uint32_t)(2 * buf + 1) * STG_ELEMS * 2;
#pragma unroll
        for (int i = 0; i < 4; i++) {
            int lin = tid + i * 256;
            int r  = lin >> 3;
            int c8 = lin & 7;
            const uint16_t* gA = A  + (size_t)(m0 + r) * lda + aOff + c8 * 8;
            const uint16_t* gB = Bp + (size_t)(j0 + r) * ldb + bOff + c8 * 8;
            uint32_t sa = aBase + (uint32_t)(r * PAD + c8 * 8) * 2;
            uint32_t sb = bBase + (uint32_t)(r * PAD + c8 * 8) * 2;
            asm volatile("cp.async.cg.shared.global [%0], [%1], 16;" :: "r"(sa), "l"(gA));
            asm volatile("cp.async.cg.shared.global [%0], [%1], 16;" :: "r"(sb), "l"(gB));
        }
        asm volatile("cp.async.commit_group;" ::: "memory");
    };

    // chunks 0,1 are always in term 0 (KC >= 4 for all our shapes)
    issue_chunk(0, 0, 0);
    issue_chunk(CH, CH, 1);

    int pf_t = 0, pf_off = 2 * CH;
    if (pf_off >= K) { pf_off -= K; pf_t++; }

    const int lrow = lane & 15;
    const int kun  = lane >> 4;
    const uint32_t aRowOff = (uint32_t)((wm * 32 + lrow) * PAD + kun * 8) * 2;
    const uint32_t bRowOff = (uint32_t)((wn * 64 + lrow) * PAD + kun * 8) * 2;

    int buf = 0;
    for (int c = 0; c < NC; c++) {
        if (c + 1 < NC) asm volatile("cp.async.wait_group 1;" ::: "memory");
        else            asm volatile("cp.async.wait_group 0;" ::: "memory");
        __syncthreads();
        if (c + 2 < NC) {
            int aOff = pf_off + ((pf_t == nterms - 1) ? hlA : 0);
            int bOff = pf_off + ((nterms == 3 && pf_t == 1) ? hlB : 0);
            issue_chunk(aOff, bOff, (buf + 2) % 3);
            pf_off += CH;
            if (pf_off == K) { pf_off = 0; pf_t++; }
        }

        const uint32_t aBase = smu + (uint32_t)(2 * buf) * STG_ELEMS * 2 + aRowOff;
        const uint32_t bBase = smu + (uint32_t)(2 * buf + 1) * STG_ELEMS * 2 + bRowOff;

        uint32_t af[2][2][4];
        uint32_t bg[2][4];

        LDSM4(af[0][0], aBase);
        LDSM4(af[0][1], aBase + 16 * PAD * 2);

#pragma unroll
        for (int ks = 0; ks < 4; ks++) {
            const int cur = ks & 1, nxt = cur ^ 1;
            const uint32_t kOff = (uint32_t)(ks * 32);
            LDSM4(bg[0], bBase + kOff);
#pragma unroll
            for (int nb2 = 0; nb2 < 4; nb2++) {
                const int gc = nb2 & 1, gn = gc ^ 1;
                if (nb2 < 3) {
                    LDSM4(bg[gn], bBase + kOff + (uint32_t)((nb2 + 1) * 16 * PAD * 2));
                } else if (ks < 3) {
                    LDSM4(af[nxt][0], aBase + kOff + 32);
                    LDSM4(af[nxt][1], aBase + kOff + 32 + 16 * PAD * 2);
                }
#pragma unroll
                for (int mt = 0; mt < 2; mt++) {
                    mma16816<FI>(acc[mt][nb2 * 2],     af[cur][mt], bg[gc][0], bg[gc][2]);
                    mma16816<FI>(acc[mt][nb2 * 2 + 1], af[cur][mt], bg[gc][1], bg[gc][3]);
                }
            }
        }
        buf = (buf + 1) % 3;
    }

    // ---------------- epilogue ----------------
    const int g = lane >> 2;
    const int t = lane & 3;
    float* lsm = (float*)sm;

    if (mode == 2) {
        __syncthreads();
        if (tid < 128) lsm[tid] = 0.f;
        __syncthreads();
    }

#pragma unroll
    for (int mt = 0; mt < 2; mt++) {
        const int row0 = m0 + wm * 32 + mt * 16 + g;
        const int row1 = row0 + 8;
        float rs0 = 0.f, rs1 = 0.f, rq0 = 0.f, rq1 = 0.f;
#pragma unroll
        for (int nb = 0; nb < 8; nb++) {
            const int col = j0 + wn * 64 + nb * 8 + t * 2;
            float d0 = acc[mt][nb][0], d1 = acc[mt][nb][1];
            float d2 = acc[mt][nb][2], d3 = acc[mt][nb][3];
            if (mode == 4) {
                float* base = (float*)Cout + (size_t)bz * sC;
                *(float2*)(base + (size_t)row0 * ldc + col) = make_float2(d0, d1);
                *(float2*)(base + (size_t)row1 * ldc + col) = make_float2(d2, d3);
                rs0 += d0 + d1; rs1 += d2 + d3;
                rq0 += d0 * d0 + d1 * d1; rq1 += d2 * d2 + d3 * d3;
            } else {
                if (mode == 2) {
                    d0 = expf(d0 - 64.f); d1 = expf(d1 - 64.f);
                    d2 = expf(d2 - 64.f); d3 = expf(d3 - 64.f);
                    rs0 += d0 + d1;
                    rs1 += d2 + d3;
                } else if (mode == 3) {
                    float inv0 = s_lrow[row0 - m0];
                    float inv1 = s_lrow[row1 - m0];
                    d0 *= inv0; d1 *= inv0; d2 *= inv1; d3 *= inv1;
                }
                uint16_t* base = (uint16_t*)Cout + (size_t)bz * sC;
                uint32_t lp0, lp1;
                uint32_t hp0 = packsplit2<FO>(d0, d1, lp0);
                uint32_t hp1 = packsplit2<FO>(d2, d3, lp1);
                uint16_t* r0p = base + (size_t)row0 * ldc + col;
                uint16_t* r1p = base + (size_t)row1 * ldc + col;
                *(uint32_t*)(r0p)     = hp0;
                *(uint32_t*)(r0p + J) = lp0;
                *(uint32_t*)(r1p)     = hp1;
                *(uint32_t*)(r1p + J) = lp1;
            }
        }
        if (mode == 2) {
            rs0 += __shfl_xor_sync(0xFFFFFFFFu, rs0, 1);
            rs0 += __shfl_xor_sync(0xFFFFFFFFu, rs0, 2);
            rs1 += __shfl_xor_sync(0xFFFFFFFFu, rs1, 1);
            rs1 += __shfl_xor_sync(0xFFFFFFFFu, rs1, 2);
            if (t == 0) {
                atomicAdd(&lsm[wm * 32 + mt * 16 + g], rs0);
                atomicAdd(&lsm[wm * 32 + mt * 16 + g + 8], rs1);
            }
        } else if (mode == 4) {
            rs0 += __shfl_xor_sync(0xFFFFFFFFu, rs0, 1);
            rs0 += __shfl_xor_sync(0xFFFFFFFFu, rs0, 2);
            rs1 += __shfl_xor_sync(0xFFFFFFFFu, rs1, 1);
            rs1 += __shfl_xor_sync(0xFFFFFFFFu, rs1, 2);
            rq0 += __shfl_xor_sync(0xFFFFFFFFu, rq0, 1);
            rq0 += __shfl_xor_sync(0xFFFFFFFFu, rq0, 2);
            rq1 += __shfl_xor_sync(0xFFFFFFFFu, rq1, 1);
            rq1 += __shfl_xor_sync(0xFFFFFFFFu, rq1, 2);
            if (t == 0) {
                int r0 = wm * 32 + mt * 16 + g, r1 = r0 + 8;
                atomicAdd(&s_ch[r0], (ull)(long long)llrintf(rs0 * (float)SC1));
                atomicAdd(&s_ch[r1], (ull)(long long)llrintf(rs1 * (float)SC1));
                atomicAdd(&s_ch[128 + r0], (ull)(long long)llrintf(rq0 * (float)SC2));
                atomicAdd(&s_ch[128 + r1], (ull)(long long)llrintf(rq1 * (float)SC2));
            }
        }
    }

    if (mode == 2) {
        __syncthreads();
        if (tid < 128)
            laux[((size_t)bz * N_ + m0 + tid) * 16 + blockIdx.x] = lsm[tid];
    } else if (mode == 4) {
        __syncthreads();
        if (tid < 128) {
            atomicAdd(&d_bnsum [m0 + tid], s_ch[tid]);
            atomicAdd(&d_bnsum2[m0 + tid], s_ch[128 + tid]);
        }
    }
}

// ---------------- BN scale/shift from fixed-point sums ----------------
__global__ void bn_stats2_kernel(const float* __restrict__ gamma,
                                 const float* __restrict__ beta,
                                 float* __restrict__ scale,
                                 float* __restrict__ shift)
{
    int c = blockIdx.x * blockDim.x + threadIdx.x;
    if (c >= C_) return;
    const double M = (double)(B_ * N_);
    double mean = (double)(long long)d_bnsum[c]  / SC1 / M;
    double ms   = (double)(long long)d_bnsum2[c] / SC2 / M;
    double var  = ms - mean * mean;
    double inv  = 1.0 / sqrt(var + 1e-5);
    double sc   = (double)gamma[c] * inv;
    scale[c] = (float)sc;
    shift[c] = (float)((double)beta[c] - mean * sc);
}

// ---------------- finalize ----------------
__global__ void finalize_kernel(const float* __restrict__ zp,
                                const float* __restrict__ x,
                                const float* __restrict__ scale,
                                const float* __restrict__ shift,
                                float* __restrict__ out)
{
    const size_t idx4 = (size_t)blockIdx.x * blockDim.x + threadIdx.x;
    const size_t total4 = (size_t)B_ * C_ * N_ / 4;
    if (idx4 >= total4) return;
    const int nq = N_ / 4;
    int n4 = (int)(idx4 % nq);
    int c  = (int)((idx4 / nq) % C_);
    int b  = (int)(idx4 / ((size_t)nq * C_));

    float4 z = ((const float4*)zp)[(size_t)c * (B_ * N_ / 4) + (size_t)b * nq + n4];
    float4 xv = ((const float4*)x)[idx4];
    const float sc = scale[c], sh = shift[c];
    float4 o;
    o.x = z.x * sc + sh + xv.x;
    o.y = z.y * sc + sh + xv.y;
    o.z = z.z * sc + sh + xv.z;
    o.w = z.w * sc + sh + xv.w;
    ((float4*)out)[idx4] = o;
}

// ---------------- launch ----------------
template <typename T>
static T* sym_addr(const void* sym)
{
    void* p = nullptr;
    cudaGetSymbolAddress(&p, sym);
    return (T*)p;
}

extern "C" void kernel_launch(void* const* d_in, const int* in_sizes, int n_in,
                              void* d_out, int out_size)
{
    const float* x     = (const float*)d_in[0];
    const float* Wg    = (const float*)d_in[1];
    const float* Wth   = (const float*)d_in[2];
    const float* Wph   = (const float*)d_in[3];
    const float* Wz    = (const float*)d_in[4];
    const float* gamma = (const float*)d_in[5];
    const float* beta  = (const float*)d_in[6];
    float* out = (float*)d_out;

    __half*  xs  = sym_addr<__half>(d_xs);
    __half*  Wtp = sym_addr<__half>(d_Wtp);
    __half*  WgS = sym_addr<__half>(d_WgS);
    __half*  WzS = sym_addr<__half>(d_WzS);
    __half*  tp  = sym_addr<__half>(d_tp);
    __half*  OS  = sym_addr<__half>(d_OS);
    uint16_t* gS = sym_addr<uint16_t>(d_gS);
    uint16_t* E  = sym_addr<uint16_t>(d_E);
    float*   lp  = sym_addr<float>(d_lpar);
    float* zp    = sym_addr<float>(d_zp);
    float* scale = sym_addr<float>(d_scale);
    float* shift = sym_addr<float>(d_shift);

    cudaFuncSetAttribute(gemm_mma_kernel<1, 1>,
                         cudaFuncAttributeMaxDynamicSharedMemorySize, GEMM_SMEM);
    cudaFuncSetAttribute(gemm_mma_kernel<1, 0>,
                         cudaFuncAttributeMaxDynamicSharedMemorySize, GEMM_SMEM);
    cudaFuncSetAttribute(gemm_mma_kernel<0, 1>,
                         cudaFuncAttributeMaxDynamicSharedMemorySize, GEMM_SMEM);

    // 1) weight splits (fp16 limbs) + zero bn accumulators
    split_all_kernel<<<dim3((P_ * C_ + 255) / 256, 4), 256>>>(
        Wth, Wph, Wg, Wz, Wtp, WgS, WzS);
    // 2) x transpose + split (fp16 limbs)
    xsplit_kernel<<<dim3(N_ / 32, C_ / 32, B_), dim3(32, 32)>>>(x, xs);

    // 3) theta+phi merged (fp16 in, fp16 limbs out), 3 terms
    gemm_mma_kernel<1, 1><<<dim3((2 * P_) / 128, N_ / 128, B_), 256, GEMM_SMEM>>>(
        (const uint16_t*)xs, 2 * C_, C_, (const uint16_t*)Wtp, 2 * C_, C_,
        tp, 4 * P_, C_, 1, 2 * P_, 3,
        (size_t)N_ * 2 * C_, 0, (size_t)N_ * 4 * P_, nullptr);
    // 4) g^T (fp16 in, bf16 limbs out — must match E's type for PV), 2 terms
    gemm_mma_kernel<1, 0><<<dim3(N_ / 128, P_ / 128, B_), 256, GEMM_SMEM>>>(
        (const uint16_t*)WgS, 2 * C_, C_, (const uint16_t*)xs, 2 * C_, C_,
        gS, 2 * N_, C_, 1, N_, 2,
        0, (size_t)N_ * 2 * C_, (size_t)P_ * 2 * N_, nullptr);
    // 5) scores (fp16 in) -> E bf16 + row partial sums, 3 terms
    gemm_mma_kernel<1, 0><<<dim3(N_ / 128, N_ / 128, B_), 256, GEMM_SMEM>>>(
        (const uint16_t*)tp, 4 * P_, 2 * P_, (const uint16_t*)(tp + P_), 4 * P_, 2 * P_,
        E, 2 * N_, P_, 2, N_, 3,
        (size_t)N_ * 4 * P_, (size_t)N_ * 4 * P_, (size_t)N_ * 2 * N_, lp);
    // 6) PV (bf16 in, fp16 limbs out): O = (E x g) / l, 3 terms
    gemm_mma_kernel<0, 1><<<dim3(P_ / 128, N_ / 128, B_), 256, GEMM_SMEM>>>(
        E, 2 * N_, N_, gS, 2 * N_, N_,
        OS, 2 * P_, N_, 3, P_, 3,
        (size_t)N_ * 2 * N_, (size_t)P_ * 2 * N_, (size_t)N_ * 2 * P_, lp);
    // 7) z (fp16 in) fp32 out + fused BN channel sums, 2 terms
    gemm_mma_kernel<1, 0><<<dim3((B_ * N_) / 128, C_ / 128, 1), 256, GEMM_SMEM>>>(
        (const uint16_t*)WzS, 2 * P_, P_, (const uint16_t*)OS, 2 * P_, P_,
        zp, B_ * N_, P_, 4, 0, 2,
        0, 0, 0, nullptr);
    // 8) BN scale/shift
    bn_stats2_kernel<<<2, 256>>>(gamma, beta, scale, shift);
    // 9) finalize
    {
        const int total4 = B_ * C_ * N_ / 4;
        finalize_kernel<<<(total4 + 255) / 256, 256>>>(zp, x, scale, shift, out);
    }
}

// round 13
// speedup vs baseline: 1.4290x; 1.0657x over previous
#include <cuda_runtime.h>
#include <cuda_bf16.h>
#include <cuda_fp16.h>
#include <math.h>
#include <stdint.h>

// Problem constants
#define B_ 8
#define C_ 512
#define N_ 2048
#define P_ 256

typedef unsigned long long ull;

// ---------------- scratch ----------------
// fp16 limb buffers
__device__ __half d_xs [(size_t)B_ * N_ * 2 * C_];  // x^T split [b][n][hi(C)|lo(C)]
__device__ __half d_Wtp[(2 * P_) * 2 * C_];         // rows: th(0..255), ph(256..511)
__device__ __half d_WgS[P_ * 2 * C_];
__device__ __half d_WzS[C_ * 2 * P_];
__device__ __half d_tp [(size_t)B_ * N_ * 4 * P_];  // [b][n][hi(2P)|lo(2P)]
__device__ __half d_OS [(size_t)B_ * N_ * 2 * P_];
// bf16 buffers (E needs bf16 range; gS must match E's type in PV)
__device__ __nv_bfloat16 d_gS[(size_t)B_ * P_ * 2 * N_]; // g^T [b][p][hi(N)|lo(N)]
__device__ __nv_bfloat16 d_E [(size_t)B_ * N_ * 2 * N_]; // exp(S-64) split
__device__ float d_lpar[(size_t)B_ * N_ * 16];           // per-jtile row sums
__device__ float d_zp[(size_t)C_ * B_ * N_];             // z channel-major [C][B*N]
__device__ ull  d_bnsum [C_];
__device__ ull  d_bnsum2[C_];
__device__ float d_scale[C_];
__device__ float d_shift[C_];

#define SC1 4194304.0   // 2^22 for sum(z)
#define SC2 65536.0     // 2^16 for sum(z^2)

// ---------------- helpers ----------------
__device__ __forceinline__ uint32_t smem_to_u32(const void* p) {
    uint32_t a;
    asm("{ .reg .u64 t; cvta.to.shared.u64 t, %1; cvt.u32.u64 %0, t; }" : "=r"(a) : "l"(p));
    return a;
}
__device__ __forceinline__ void split2h(float v, __half& h, __half& l) {
    h = __float2half(v);
    l = __float2half(v - __half2float(h));
}
// pack split pair; FO=1 -> fp16 limbs, FO=0 -> bf16 limbs
template <int FO>
__device__ __forceinline__ uint32_t packsplit2(float a, float b, uint32_t& lo) {
    if (FO) {
        __half h0, l0, h1, l1;
        split2h(a, h0, l0); split2h(b, h1, l1);
        lo = (uint32_t)__half_as_ushort(l0) | ((uint32_t)__half_as_ushort(l1) << 16);
        return (uint32_t)__half_as_ushort(h0) | ((uint32_t)__half_as_ushort(h1) << 16);
    } else {
        __nv_bfloat16 h0 = __float2bfloat16(a);
        __nv_bfloat16 l0 = __float2bfloat16(a - __bfloat162float(h0));
        __nv_bfloat16 h1 = __float2bfloat16(b);
        __nv_bfloat16 l1 = __float2bfloat16(b - __bfloat162float(h1));
        lo = (uint32_t)__bfloat16_as_ushort(l0) | ((uint32_t)__bfloat16_as_ushort(l1) << 16);
        return (uint32_t)__bfloat16_as_ushort(h0) | ((uint32_t)__bfloat16_as_ushort(h1) << 16);
    }
}

// ---------------- weight splits (one launch) ----------------
__global__ void split_all_kernel(const float* __restrict__ Wth, const float* __restrict__ Wph,
                                 const float* __restrict__ Wg,  const float* __restrict__ Wz,
                                 __half* __restrict__ Wtp,
                                 __half* __restrict__ WgS, __half* __restrict__ WzS)
{
    const int which = blockIdx.y;
    const int idx = blockIdx.x * blockDim.x + threadIdx.x;
    if (idx >= P_ * C_) return;
    const float* in;
    __half* out;
    int K, rofs = 0;
    if      (which == 0) { in = Wth; out = Wtp; K = C_; }
    else if (which == 1) { in = Wph; out = Wtp; K = C_; rofs = P_; }
    else if (which == 2) { in = Wg;  out = WgS; K = C_; }
    else                 { in = Wz;  out = WzS; K = P_;
                           if (idx < C_) { d_bnsum[idx] = 0ull; d_bnsum2[idx] = 0ull; } }
    int r = idx / K, k = idx % K;
    __half h, l;
    split2h(in[idx], h, l);
    __half* o = out + (size_t)(r + rofs) * (2 * K);
    o[k] = h;
    o[K + k] = l;
}

// ---------------- x transpose + split (fp16) ----------------
__global__ void xsplit_kernel(const float* __restrict__ x,
                              __half* __restrict__ xs)
{
    __shared__ float t[32][33];
    const int b = blockIdx.z;
    const int n0 = blockIdx.x * 32, c0 = blockIdx.y * 32;
    const int tx = threadIdx.x, ty = threadIdx.y;
    const float* xb = x + (size_t)b * C_ * N_;
    t[ty][tx] = xb[(size_t)(c0 + ty) * N_ + n0 + tx];
    __syncthreads();
    float v = t[tx][ty];
    int n = n0 + ty, c = c0 + tx;
    __half h, l;
    split2h(v, h, l);
    size_t row = ((size_t)b * N_ + n) * (size_t)(2 * C_);
    xs[row + c] = h;
    xs[row + C_ + c] = l;
}

// ---------------- mma.sync split GEMM (templated on in/out limb type) ----------------
// C[i,j] = sum over nterms t of sum_k A[i, aoff(t)+k] * B[j, boff(t)+k], k in [0,K)
//   nterms=3: (hi,hi),(hi,lo),(lo,hi)     aoff = t==2?hlA:0 ; boff = t==1?hlB:0
//   nterms=2: (hi,hi),(lo,hi)             aoff = t==1?hlA:0 ; boff = 0
//   nterms=1: (hi,hi)                     aoff = boff = 0
// FI: 1 = fp16 operands, 0 = bf16 operands. FO: limb type for split outputs.
// mode: 1 = split [hi|lo] out; 2 = exp(acc-64) split + row partial sums (laux);
//       3 = scale by 1/rowsum(laux partials), split out; 4 = fp32 out + BN channel sums.
#define CH 64
#define PAD 72
#define STG_ELEMS (128 * PAD)
#define GEMM_SMEM (6 * STG_ELEMS * 2)

#define LDSM4(d, addr) \
    asm volatile("ldmatrix.sync.aligned.m8n8.x4.shared.b16 {%0,%1,%2,%3}, [%4];" \
        : "=r"((d)[0]), "=r"((d)[1]), "=r"((d)[2]), "=r"((d)[3]) : "r"(addr))

template <int FI>
__device__ __forceinline__ void mma16816(float ac[4], const uint32_t a[4],
                                         uint32_t b0, uint32_t b1) {
    if (FI) {
        asm volatile("mma.sync.aligned.m16n8k16.row.col.f32.f16.f16.f32 "
            "{%0,%1,%2,%3}, {%4,%5,%6,%7}, {%8,%9}, {%0,%1,%2,%3};"
            : "+f"(ac[0]), "+f"(ac[1]), "+f"(ac[2]), "+f"(ac[3])
            : "r"(a[0]), "r"(a[1]), "r"(a[2]), "r"(a[3]), "r"(b0), "r"(b1));
    } else {
        asm volatile("mma.sync.aligned.m16n8k16.row.col.f32.bf16.bf16.f32 "
            "{%0,%1,%2,%3}, {%4,%5,%6,%7}, {%8,%9}, {%0,%1,%2,%3};"
            : "+f"(ac[0]), "+f"(ac[1]), "+f"(ac[2]), "+f"(ac[3])
            : "r"(a[0]), "r"(a[1]), "r"(a[2]), "r"(a[3]), "r"(b0), "r"(b1));
    }
}

template <int FI, int FO>
__global__ void __launch_bounds__(256, 2) gemm_mma_kernel(
    const uint16_t* __restrict__ A, int lda, int hlA,
    const uint16_t* __restrict__ Bp, int ldb, int hlB,
    void* __restrict__ Cout, int ldc, int K, int mode, int J, int nterms,
    size_t sA, size_t sB, size_t sC, float* __restrict__ laux)
{
    extern __shared__ uint16_t sm[];
    __shared__ ull  s_ch[256];
    __shared__ float s_lrow[128];
    const uint32_t smu = smem_to_u32(sm);

    const int tid  = threadIdx.x;
    const int wid  = tid >> 5;
    const int lane = tid & 31;
    const int wm = wid & 3;
    const int wn = wid >> 2;
    const int bz = blockIdx.z;
    A  += (size_t)bz * sA;
    Bp += (size_t)bz * sB;
    const int m0 = blockIdx.y * 128;
    const int j0 = blockIdx.x * 128;

    if (mode == 3 && tid < 128) {
        const float* p = laux + ((size_t)bz * N_ + m0 + tid) * 16;
        float s = 0.f;
#pragma unroll
        for (int j = 0; j < 16; j++) s += p[j];
        s_lrow[tid] = 1.f / s;
    }
    if (mode == 4 && tid < 256) s_ch[tid] = 0ull;

    float acc[2][8][4];
#pragma unroll
    for (int mt = 0; mt < 2; mt++)
#pragma unroll
        for (int nb = 0; nb < 8; nb++)
#pragma unroll
            for (int q = 0; q < 4; q++) acc[mt][nb][q] = 0.f;

    const int KC = K / CH;
    const int NC = nterms * KC;

    auto issue_chunk = [&](int aOff, int bOff, int buf) {
        const uint32_t aBase = smu + (uint32_t)(2 * buf) * STG_ELEMS * 2;
        const uint32_t bBase = smu + (uint32_t)(2 * buf + 1) * STG_ELEMS * 2;
#pragma unroll
        for (int i = 0; i < 4; i++) {
            int lin = tid + i * 256;
            int r  = lin >> 3;
            int c8 = lin & 7;
            const uint16_t* gA = A  + (size_t)(m0 + r) * lda + aOff + c8 * 8;
            const uint16_t* gB = Bp + (size_t)(j0 + r) * ldb + bOff + c8 * 8;
            uint32_t sa = aBase + (uint32_t)(r * PAD + c8 * 8) * 2;
            uint32_t sb = bBase + (uint32_t)(r * PAD + c8 * 8) * 2;
            asm volatile("cp.async.cg.shared.global [%0], [%1], 16;" :: "r"(sa), "l"(gA));
            asm volatile("cp.async.cg.shared.global [%0], [%1], 16;" :: "r"(sb), "l"(gB));
        }
        asm volatile("cp.async.commit_group;" ::: "memory");
    };

    // chunks 0,1 are always in term 0 (KC >= 4 for all our shapes; NC >= 4)
    issue_chunk(0, 0, 0);
    issue_chunk(CH, CH, 1);

    int pf_t = 0, pf_off = 2 * CH;
    if (pf_off >= K) { pf_off -= K; pf_t++; }

    const int lrow = lane & 15;
    const int kun  = lane >> 4;
    const uint32_t aRowOff = (uint32_t)((wm * 32 + lrow) * PAD + kun * 8) * 2;
    const uint32_t bRowOff = (uint32_t)((wn * 64 + lrow) * PAD + kun * 8) * 2;

    int buf = 0;
    for (int c = 0; c < NC; c++) {
        if (c + 1 < NC) asm volatile("cp.async.wait_group 1;" ::: "memory");
        else            asm volatile("cp.async.wait_group 0;" ::: "memory");
        __syncthreads();
        if (c + 2 < NC) {
            int aOff = pf_off + ((nterms >= 2 && pf_t == nterms - 1) ? hlA : 0);
            int bOff = pf_off + ((nterms == 3 && pf_t == 1) ? hlB : 0);
            issue_chunk(aOff, bOff, (buf + 2) % 3);
            pf_off += CH;
            if (pf_off == K) { pf_off = 0; pf_t++; }
        }

        const uint32_t aBase = smu + (uint32_t)(2 * buf) * STG_ELEMS * 2 + aRowOff;
        const uint32_t bBase = smu + (uint32_t)(2 * buf + 1) * STG_ELEMS * 2 + bRowOff;

        uint32_t af[2][2][4];
        uint32_t bg[2][4];

        LDSM4(af[0][0], aBase);
        LDSM4(af[0][1], aBase + 16 * PAD * 2);

#pragma unroll
        for (int ks = 0; ks < 4; ks++) {
            const int cur = ks & 1, nxt = cur ^ 1;
            const uint32_t kOff = (uint32_t)(ks * 32);
            LDSM4(bg[0], bBase + kOff);
#pragma unroll
            for (int nb2 = 0; nb2 < 4; nb2++) {
                const int gc = nb2 & 1, gn = gc ^ 1;
                if (nb2 < 3) {
                    LDSM4(bg[gn], bBase + kOff + (uint32_t)((nb2 + 1) * 16 * PAD * 2));
                } else if (ks < 3) {
                    LDSM4(af[nxt][0], aBase + kOff + 32);
                    LDSM4(af[nxt][1], aBase + kOff + 32 + 16 * PAD * 2);
                }
#pragma unroll
                for (int mt = 0; mt < 2; mt++) {
                    mma16816<FI>(acc[mt][nb2 * 2],     af[cur][mt], bg[gc][0], bg[gc][2]);
                    mma16816<FI>(acc[mt][nb2 * 2 + 1], af[cur][mt], bg[gc][1], bg[gc][3]);
                }
            }
        }
        buf = (buf + 1) % 3;
    }

    // ---------------- epilogue ----------------
    const int g = lane >> 2;
    const int t = lane & 3;
    float* lsm = (float*)sm;

    if (mode == 2) {
        __syncthreads();
        if (tid < 128) lsm[tid] = 0.f;
        __syncthreads();
    }

#pragma unroll
    for (int mt = 0; mt < 2; mt++) {
        const int row0 = m0 + wm * 32 + mt * 16 + g;
        const int row1 = row0 + 8;
        float rs0 = 0.f, rs1 = 0.f, rq0 = 0.f, rq1 = 0.f;
#pragma unroll
        for (int nb = 0; nb < 8; nb++) {
            const int col = j0 + wn * 64 + nb * 8 + t * 2;
            float d0 = acc[mt][nb][0], d1 = acc[mt][nb][1];
            float d2 = acc[mt][nb][2], d3 = acc[mt][nb][3];
            if (mode == 4) {
                float* base = (float*)Cout + (size_t)bz * sC;
                *(float2*)(base + (size_t)row0 * ldc + col) = make_float2(d0, d1);
                *(float2*)(base + (size_t)row1 * ldc + col) = make_float2(d2, d3);
                rs0 += d0 + d1; rs1 += d2 + d3;
                rq0 += d0 * d0 + d1 * d1; rq1 += d2 * d2 + d3 * d3;
            } else {
                if (mode == 2) {
                    d0 = expf(d0 - 64.f); d1 = expf(d1 - 64.f);
                    d2 = expf(d2 - 64.f); d3 = expf(d3 - 64.f);
                    rs0 += d0 + d1;
                    rs1 += d2 + d3;
                } else if (mode == 3) {
                    float inv0 = s_lrow[row0 - m0];
                    float inv1 = s_lrow[row1 - m0];
                    d0 *= inv0; d1 *= inv0; d2 *= inv1; d3 *= inv1;
                }
                uint16_t* base = (uint16_t*)Cout + (size_t)bz * sC;
                uint32_t lp0, lp1;
                uint32_t hp0 = packsplit2<FO>(d0, d1, lp0);
                uint32_t hp1 = packsplit2<FO>(d2, d3, lp1);
                uint16_t* r0p = base + (size_t)row0 * ldc + col;
                uint16_t* r1p = base + (size_t)row1 * ldc + col;
                *(uint32_t*)(r0p)     = hp0;
                *(uint32_t*)(r0p + J) = lp0;
                *(uint32_t*)(r1p)     = hp1;
                *(uint32_t*)(r1p + J) = lp1;
            }
        }
        if (mode == 2) {
            rs0 += __shfl_xor_sync(0xFFFFFFFFu, rs0, 1);
            rs0 += __shfl_xor_sync(0xFFFFFFFFu, rs0, 2);
            rs1 += __shfl_xor_sync(0xFFFFFFFFu, rs1, 1);
            rs1 += __shfl_xor_sync(0xFFFFFFFFu, rs1, 2);
            if (t == 0) {
                atomicAdd(&lsm[wm * 32 + mt * 16 + g], rs0);
                atomicAdd(&lsm[wm * 32 + mt * 16 + g + 8], rs1);
            }
        } else if (mode == 4) {
            rs0 += __shfl_xor_sync(0xFFFFFFFFu, rs0, 1);
            rs0 += __shfl_xor_sync(0xFFFFFFFFu, rs0, 2);
            rs1 += __shfl_xor_sync(0xFFFFFFFFu, rs1, 1);
            rs1 += __shfl_xor_sync(0xFFFFFFFFu, rs1, 2);
            rq0 += __shfl_xor_sync(0xFFFFFFFFu, rq0, 1);
            rq0 += __shfl_xor_sync(0xFFFFFFFFu, rq0, 2);
            rq1 += __shfl_xor_sync(0xFFFFFFFFu, rq1, 1);
            rq1 += __shfl_xor_sync(0xFFFFFFFFu, rq1, 2);
            if (t == 0) {
                int r0 = wm * 32 + mt * 16 + g, r1 = r0 + 8;
                atomicAdd(&s_ch[r0], (ull)(long long)llrintf(rs0 * (float)SC1));
                atomicAdd(&s_ch[r1], (ull)(long long)llrintf(rs1 * (float)SC1));
                atomicAdd(&s_ch[128 + r0], (ull)(long long)llrintf(rq0 * (float)SC2));
                atomicAdd(&s_ch[128 + r1], (ull)(long long)llrintf(rq1 * (float)SC2));
            }
        }
    }

    if (mode == 2) {
        __syncthreads();
        if (tid < 128)
            laux[((size_t)bz * N_ + m0 + tid) * 16 + blockIdx.x] = lsm[tid];
    } else if (mode == 4) {
        __syncthreads();
        if (tid < 128) {
            atomicAdd(&d_bnsum [m0 + tid], s_ch[tid]);
            atomicAdd(&d_bnsum2[m0 + tid], s_ch[128 + tid]);
        }
    }
}

// ---------------- BN scale/shift from fixed-point sums ----------------
__global__ void bn_stats2_kernel(const float* __restrict__ gamma,
                                 const float* __restrict__ beta,
                                 float* __restrict__ scale,
                                 float* __restrict__ shift)
{
    int c = blockIdx.x * blockDim.x + threadIdx.x;
    if (c >= C_) return;
    const double M = (double)(B_ * N_);
    double mean = (double)(long long)d_bnsum[c]  / SC1 / M;
    double ms   = (double)(long long)d_bnsum2[c] / SC2 / M;
    double var  = ms - mean * mean;
    double inv  = 1.0 / sqrt(var + 1e-5);
    double sc   = (double)gamma[c] * inv;
    scale[c] = (float)sc;
    shift[c] = (float)((double)beta[c] - mean * sc);
}

// ---------------- finalize ----------------
__global__ void finalize_kernel(const float* __restrict__ zp,
                                const float* __restrict__ x,
                                const float* __restrict__ scale,
                                const float* __restrict__ shift,
                                float* __restrict__ out)
{
    const size_t idx4 = (size_t)blockIdx.x * blockDim.x + threadIdx.x;
    const size_t total4 = (size_t)B_ * C_ * N_ / 4;
    if (idx4 >= total4) return;
    const int nq = N_ / 4;
    int n4 = (int)(idx4 % nq);
    int c  = (int)((idx4 / nq) % C_);
    int b  = (int)(idx4 / ((size_t)nq * C_));

    float4 z = ((const float4*)zp)[(size_t)c * (B_ * N_ / 4) + (size_t)b * nq + n4];
    float4 xv = ((const float4*)x)[idx4];
    const float sc = scale[c], sh = shift[c];
    float4 o;
    o.x = z.x * sc + sh + xv.x;
    o.y = z.y * sc + sh + xv.y;
    o.z = z.z * sc + sh + xv.z;
    o.w = z.w * sc + sh + xv.w;
    ((float4*)out)[idx4] = o;
}

// ---------------- launch ----------------
template <typename T>
static T* sym_addr(const void* sym)
{
    void* p = nullptr;
    cudaGetSymbolAddress(&p, sym);
    return (T*)p;
}

extern "C" void kernel_launch(void* const* d_in, const int* in_sizes, int n_in,
                              void* d_out, int out_size)
{
    const float* x     = (const float*)d_in[0];
    const float* Wg    = (const float*)d_in[1];
    const float* Wth   = (const float*)d_in[2];
    const float* Wph   = (const float*)d_in[3];
    const float* Wz    = (const float*)d_in[4];
    const float* gamma = (const float*)d_in[5];
    const float* beta  = (const float*)d_in[6];
    float* out = (float*)d_out;

    __half*  xs  = sym_addr<__half>(d_xs);
    __half*  Wtp = sym_addr<__half>(d_Wtp);
    __half*  WgS = sym_addr<__half>(d_WgS);
    __half*  WzS = sym_addr<__half>(d_WzS);
    __half*  tp  = sym_addr<__half>(d_tp);
    __half*  OS  = sym_addr<__half>(d_OS);
    uint16_t* gS = sym_addr<uint16_t>(d_gS);
    uint16_t* E  = sym_addr<uint16_t>(d_E);
    float*   lp  = sym_addr<float>(d_lpar);
    float* zp    = sym_addr<float>(d_zp);
    float* scale = sym_addr<float>(d_scale);
    float* shift = sym_addr<float>(d_shift);

    cudaFuncSetAttribute(gemm_mma_kernel<1, 1>,
                         cudaFuncAttributeMaxDynamicSharedMemorySize, GEMM_SMEM);
    cudaFuncSetAttribute(gemm_mma_kernel<1, 0>,
                         cudaFuncAttributeMaxDynamicSharedMemorySize, GEMM_SMEM);
    cudaFuncSetAttribute(gemm_mma_kernel<0, 1>,
                         cudaFuncAttributeMaxDynamicSharedMemorySize, GEMM_SMEM);

    // 1) weight splits (fp16 limbs) + zero bn accumulators
    split_all_kernel<<<dim3((P_ * C_ + 255) / 256, 4), 256>>>(
        Wth, Wph, Wg, Wz, Wtp, WgS, WzS);
    // 2) x transpose + split (fp16 limbs)
    xsplit_kernel<<<dim3(N_ / 32, C_ / 32, B_), dim3(32, 32)>>>(x, xs);

    // 3) theta+phi merged (fp16 in, fp16 limbs out), 3 terms
    gemm_mma_kernel<1, 1><<<dim3((2 * P_) / 128, N_ / 128, B_), 256, GEMM_SMEM>>>(
        (const uint16_t*)xs, 2 * C_, C_, (const uint16_t*)Wtp, 2 * C_, C_,
        tp, 4 * P_, C_, 1, 2 * P_, 3,
        (size_t)N_ * 2 * C_, 0, (size_t)N_ * 4 * P_, nullptr);
    // 4) g^T (fp16 in, bf16 limbs out), 1 term (hi x hi only)
    gemm_mma_kernel<1, 0><<<dim3(N_ / 128, P_ / 128, B_), 256, GEMM_SMEM>>>(
        (const uint16_t*)WgS, 2 * C_, C_, (const uint16_t*)xs, 2 * C_, C_,
        gS, 2 * N_, C_, 1, N_, 1,
        0, (size_t)N_ * 2 * C_, (size_t)P_ * 2 * N_, nullptr);
    // 5) scores (fp16 in) -> E bf16 + row partial sums, 3 terms
    gemm_mma_kernel<1, 0><<<dim3(N_ / 128, N_ / 128, B_), 256, GEMM_SMEM>>>(
        (const uint16_t*)tp, 4 * P_, 2 * P_, (const uint16_t*)(tp + P_), 4 * P_, 2 * P_,
        E, 2 * N_, P_, 2, N_, 3,
        (size_t)N_ * 4 * P_, (size_t)N_ * 4 * P_, (size_t)N_ * 2 * N_, lp);
    // 6) PV (bf16 in, fp16 limbs out): O = (E x g) / l, 3 terms
    gemm_mma_kernel<0, 1><<<dim3(P_ / 128, N_ / 128, B_), 256, GEMM_SMEM>>>(
        E, 2 * N_, N_, gS, 2 * N_, N_,
        OS, 2 * P_, N_, 3, P_, 3,
        (size_t)N_ * 2 * N_, (size_t)P_ * 2 * N_, (size_t)N_ * 2 * P_, lp);
    // 7) z (fp16 in) fp32 out + fused BN channel sums, 1 term
    gemm_mma_kernel<1, 0><<<dim3((B_ * N_) / 128, C_ / 128, 1), 256, GEMM_SMEM>>>(
        (const uint16_t*)WzS, 2 * P_, P_, (const uint16_t*)OS, 2 * P_, P_,
        zp, B_ * N_, P_, 4, 0, 1,
        0, 0, 0, nullptr);
    // 8) BN scale/shift
    bn_stats2_kernel<<<2, 256>>>(gamma, beta, scale, shift);
    // 9) finalize
    {
        const int total4 = B_ * C_ * N_ / 4;
        finalize_kernel<<<(total4 + 255) / 256, 256>>>(zp, x, scale, shift, out);
    }
}

// round 14
// speedup vs baseline: 1.5071x; 1.0546x over previous
#include <cuda_runtime.h>
#include <cuda_bf16.h>
#include <cuda_fp16.h>
#include <math.h>
#include <stdint.h>

// Problem constants
#define B_ 8
#define C_ 512
#define N_ 2048
#define P_ 256

typedef unsigned long long ull;

// ---------------- scratch ----------------
// fp16 limb buffers
__device__ __half d_xs [(size_t)B_ * N_ * 2 * C_];  // x^T split [b][n][hi(C)|lo(C)]
__device__ __half d_Wtp[(2 * P_) * 2 * C_];         // rows: th(0..255), ph(256..511)
__device__ __half d_WgS[P_ * 2 * C_];
__device__ __half d_WzS[C_ * 2 * P_];
__device__ __half d_tp [(size_t)B_ * N_ * 4 * P_];  // [b][n][hi(2P)|lo(2P)]
__device__ __half d_gS [(size_t)B_ * P_ * 2 * N_];  // g^T [b][p][hi(N)|lo(N)] fp16 limbs
__device__ __half d_OS [(size_t)B_ * N_ * 2 * P_];
__device__ __half d_P  [(size_t)B_ * N_ * N_];      // normalized probs fp16 (single limb)
// bf16 buffers (E needs bf16 range pre-normalization)
__device__ __nv_bfloat16 d_E [(size_t)B_ * N_ * 2 * N_]; // exp(S-64) split
__device__ float d_lpar[(size_t)B_ * N_ * 16];           // per-jtile row sums
__device__ float d_zp[(size_t)C_ * B_ * N_];             // z channel-major [C][B*N]
__device__ ull  d_bnsum [C_];
__device__ ull  d_bnsum2[C_];
__device__ float d_scale[C_];
__device__ float d_shift[C_];

#define SC1 4194304.0   // 2^22 for sum(z)
#define SC2 65536.0     // 2^16 for sum(z^2)

// ---------------- helpers ----------------
__device__ __forceinline__ uint32_t smem_to_u32(const void* p) {
    uint32_t a;
    asm("{ .reg .u64 t; cvta.to.shared.u64 t, %1; cvt.u32.u64 %0, t; }" : "=r"(a) : "l"(p));
    return a;
}
__device__ __forceinline__ void split2h(float v, __half& h, __half& l) {
    h = __float2half(v);
    l = __float2half(v - __half2float(h));
}
// pack split pair; FO=1 -> fp16 limbs, FO=0 -> bf16 limbs
template <int FO>
__device__ __forceinline__ uint32_t packsplit2(float a, float b, uint32_t& lo) {
    if (FO) {
        __half h0, l0, h1, l1;
        split2h(a, h0, l0); split2h(b, h1, l1);
        lo = (uint32_t)__half_as_ushort(l0) | ((uint32_t)__half_as_ushort(l1) << 16);
        return (uint32_t)__half_as_ushort(h0) | ((uint32_t)__half_as_ushort(h1) << 16);
    } else {
        __nv_bfloat16 h0 = __float2bfloat16(a);
        __nv_bfloat16 l0 = __float2bfloat16(a - __bfloat162float(h0));
        __nv_bfloat16 h1 = __float2bfloat16(b);
        __nv_bfloat16 l1 = __float2bfloat16(b - __bfloat162float(h1));
        lo = (uint32_t)__bfloat16_as_ushort(l0) | ((uint32_t)__bfloat16_as_ushort(l1) << 16);
        return (uint32_t)__bfloat16_as_ushort(h0) | ((uint32_t)__bfloat16_as_ushort(h1) << 16);
    }
}

// ---------------- weight splits (one launch) ----------------
__global__ void split_all_kernel(const float* __restrict__ Wth, const float* __restrict__ Wph,
                                 const float* __restrict__ Wg,  const float* __restrict__ Wz,
                                 __half* __restrict__ Wtp,
                                 __half* __restrict__ WgS, __half* __restrict__ WzS)
{
    const int which = blockIdx.y;
    const int idx = blockIdx.x * blockDim.x + threadIdx.x;
    if (idx >= P_ * C_) return;
    const float* in;
    __half* out;
    int K, rofs = 0;
    if      (which == 0) { in = Wth; out = Wtp; K = C_; }
    else if (which == 1) { in = Wph; out = Wtp; K = C_; rofs = P_; }
    else if (which == 2) { in = Wg;  out = WgS; K = C_; }
    else                 { in = Wz;  out = WzS; K = P_;
                           if (idx < C_) { d_bnsum[idx] = 0ull; d_bnsum2[idx] = 0ull; } }
    int r = idx / K, k = idx % K;
    __half h, l;
    split2h(in[idx], h, l);
    __half* o = out + (size_t)(r + rofs) * (2 * K);
    o[k] = h;
    o[K + k] = l;
}

// ---------------- x transpose + split (fp16) ----------------
__global__ void xsplit_kernel(const float* __restrict__ x,
                              __half* __restrict__ xs)
{
    __shared__ float t[32][33];
    const int b = blockIdx.z;
    const int n0 = blockIdx.x * 32, c0 = blockIdx.y * 32;
    const int tx = threadIdx.x, ty = threadIdx.y;
    const float* xb = x + (size_t)b * C_ * N_;
    t[ty][tx] = xb[(size_t)(c0 + ty) * N_ + n0 + tx];
    __syncthreads();
    float v = t[tx][ty];
    int n = n0 + ty, c = c0 + tx;
    __half h, l;
    split2h(v, h, l);
    size_t row = ((size_t)b * N_ + n) * (size_t)(2 * C_);
    xs[row + c] = h;
    xs[row + C_ + c] = l;
}

// ---------------- mma.sync split GEMM ----------------
// C[i,j] = sum over nterms t of sum_k A[i, aoff(t)+k] * B[j, boff(t)+k], k in [0,K)
//   aoff(t) = (aMask>>t & 1) ? hlA : 0 ; boff(t) = (bMask>>t & 1) ? hlB : 0
// FI: 1 = fp16 operands, 0 = bf16 operands. FO: limb type for split outputs.
// mode: 1 = split [hi|lo] out; 2 = exp(acc-64) split + row partial sums (laux);
//       4 = fp32 out + BN channel sums.
#define CH 64
#define PAD 72
#define STG_ELEMS (128 * PAD)
#define GEMM_SMEM (6 * STG_ELEMS * 2)

#define LDSM4(d, addr) \
    asm volatile("ldmatrix.sync.aligned.m8n8.x4.shared.b16 {%0,%1,%2,%3}, [%4];" \
        : "=r"((d)[0]), "=r"((d)[1]), "=r"((d)[2]), "=r"((d)[3]) : "r"(addr))

template <int FI>
__device__ __forceinline__ void mma16816(float ac[4], const uint32_t a[4],
                                         uint32_t b0, uint32_t b1) {
    if (FI) {
        asm volatile("mma.sync.aligned.m16n8k16.row.col.f32.f16.f16.f32 "
            "{%0,%1,%2,%3}, {%4,%5,%6,%7}, {%8,%9}, {%0,%1,%2,%3};"
            : "+f"(ac[0]), "+f"(ac[1]), "+f"(ac[2]), "+f"(ac[3])
            : "r"(a[0]), "r"(a[1]), "r"(a[2]), "r"(a[3]), "r"(b0), "r"(b1));
    } else {
        asm volatile("mma.sync.aligned.m16n8k16.row.col.f32.bf16.bf16.f32 "
            "{%0,%1,%2,%3}, {%4,%5,%6,%7}, {%8,%9}, {%0,%1,%2,%3};"
            : "+f"(ac[0]), "+f"(ac[1]), "+f"(ac[2]), "+f"(ac[3])
            : "r"(a[0]), "r"(a[1]), "r"(a[2]), "r"(a[3]), "r"(b0), "r"(b1));
    }
}

template <int FI, int FO>
__global__ void __launch_bounds__(256, 2) gemm_mma_kernel(
    const uint16_t* __restrict__ A, int lda, int hlA,
    const uint16_t* __restrict__ Bp, int ldb, int hlB,
    void* __restrict__ Cout, int ldc, int K, int mode, int J,
    int nterms, int aMask, int bMask,
    size_t sA, size_t sB, size_t sC, float* __restrict__ laux)
{
    extern __shared__ uint16_t sm[];
    __shared__ ull s_ch[256];
    const uint32_t smu = smem_to_u32(sm);

    const int tid  = threadIdx.x;
    const int wid  = tid >> 5;
    const int lane = tid & 31;
    const int wm = wid & 3;
    const int wn = wid >> 2;
    const int bz = blockIdx.z;
    A  += (size_t)bz * sA;
    Bp += (size_t)bz * sB;
    const int m0 = blockIdx.y * 128;
    const int j0 = blockIdx.x * 128;

    if (mode == 4 && tid < 256) s_ch[tid] = 0ull;

    float acc[2][8][4];
#pragma unroll
    for (int mt = 0; mt < 2; mt++)
#pragma unroll
        for (int nb = 0; nb < 8; nb++)
#pragma unroll
            for (int q = 0; q < 4; q++) acc[mt][nb][q] = 0.f;

    const int KC = K / CH;
    const int NC = nterms * KC;

    auto issue_chunk = [&](int aOff, int bOff, int buf) {
        const uint32_t aBase = smu + (uint32_t)(2 * buf) * STG_ELEMS * 2;
        const uint32_t bBase = smu + (uint32_t)(2 * buf + 1) * STG_ELEMS * 2;
#pragma unroll
        for (int i = 0; i < 4; i++) {
            int lin = tid + i * 256;
            int r  = lin >> 3;
            int c8 = lin & 7;
            const uint16_t* gA = A  + (size_t)(m0 + r) * lda + aOff + c8 * 8;
            const uint16_t* gB = Bp + (size_t)(j0 + r) * ldb + bOff + c8 * 8;
            uint32_t sa = aBase + (uint32_t)(r * PAD + c8 * 8) * 2;
            uint32_t sb = bBase + (uint32_t)(r * PAD + c8 * 8) * 2;
            asm volatile("cp.async.cg.shared.global [%0], [%1], 16;" :: "r"(sa), "l"(gA));
            asm volatile("cp.async.cg.shared.global [%0], [%1], 16;" :: "r"(sb), "l"(gB));
        }
        asm volatile("cp.async.commit_group;" ::: "memory");
    };

    // chunks 0,1 are always in term 0 (KC >= 4 for all our shapes); term 0 = hi/hi
    issue_chunk(0, 0, 0);
    issue_chunk(CH, CH, 1);

    int pf_t = 0, pf_off = 2 * CH;
    if (pf_off >= K) { pf_off -= K; pf_t++; }

    const int lrow = lane & 15;
    const int kun  = lane >> 4;
    const uint32_t aRowOff = (uint32_t)((wm * 32 + lrow) * PAD + kun * 8) * 2;
    const uint32_t bRowOff = (uint32_t)((wn * 64 + lrow) * PAD + kun * 8) * 2;

    int buf = 0;
    for (int c = 0; c < NC; c++) {
        if (c + 1 < NC) asm volatile("cp.async.wait_group 1;" ::: "memory");
        else            asm volatile("cp.async.wait_group 0;" ::: "memory");
        __syncthreads();
        if (c + 2 < NC) {
            int aOff = pf_off + (((aMask >> pf_t) & 1) ? hlA : 0);
            int bOff = pf_off + (((bMask >> pf_t) & 1) ? hlB : 0);
            issue_chunk(aOff, bOff, (buf + 2) % 3);
            pf_off += CH;
            if (pf_off == K) { pf_off = 0; pf_t++; }
        }

        const uint32_t aBase = smu + (uint32_t)(2 * buf) * STG_ELEMS * 2 + aRowOff;
        const uint32_t bBase = smu + (uint32_t)(2 * buf + 1) * STG_ELEMS * 2 + bRowOff;

        uint32_t af[2][2][4];
        uint32_t bg[2][4];

        LDSM4(af[0][0], aBase);
        LDSM4(af[0][1], aBase + 16 * PAD * 2);

#pragma unroll
        for (int ks = 0; ks < 4; ks++) {
            const int cur = ks & 1, nxt = cur ^ 1;
            const uint32_t kOff = (uint32_t)(ks * 32);
            LDSM4(bg[0], bBase + kOff);
#pragma unroll
            for (int nb2 = 0; nb2 < 4; nb2++) {
                const int gc = nb2 & 1, gn = gc ^ 1;
                if (nb2 < 3) {
                    LDSM4(bg[gn], bBase + kOff + (uint32_t)((nb2 + 1) * 16 * PAD * 2));
                } else if (ks < 3) {
                    LDSM4(af[nxt][0], aBase + kOff + 32);
                    LDSM4(af[nxt][1], aBase + kOff + 32 + 16 * PAD * 2);
                }
#pragma unroll
                for (int mt = 0; mt < 2; mt++) {
                    mma16816<FI>(acc[mt][nb2 * 2],     af[cur][mt], bg[gc][0], bg[gc][2]);
                    mma16816<FI>(acc[mt][nb2 * 2 + 1], af[cur][mt], bg[gc][1], bg[gc][3]);
                }
            }
        }
        buf = (buf + 1) % 3;
    }

    // ---------------- epilogue ----------------
    const int g = lane >> 2;
    const int t = lane & 3;
    float* lsm = (float*)sm;

    if (mode == 2) {
        __syncthreads();
        if (tid < 128) lsm[tid] = 0.f;
        __syncthreads();
    }

#pragma unroll
    for (int mt = 0; mt < 2; mt++) {
        const int row0 = m0 + wm * 32 + mt * 16 + g;
        const int row1 = row0 + 8;
        float rs0 = 0.f, rs1 = 0.f, rq0 = 0.f, rq1 = 0.f;
#pragma unroll
        for (int nb = 0; nb < 8; nb++) {
            const int col = j0 + wn * 64 + nb * 8 + t * 2;
            float d0 = acc[mt][nb][0], d1 = acc[mt][nb][1];
            float d2 = acc[mt][nb][2], d3 = acc[mt][nb][3];
            if (mode == 4) {
                float* base = (float*)Cout + (size_t)bz * sC;
                *(float2*)(base + (size_t)row0 * ldc + col) = make_float2(d0, d1);
                *(float2*)(base + (size_t)row1 * ldc + col) = make_float2(d2, d3);
                rs0 += d0 + d1; rs1 += d2 + d3;
                rq0 += d0 * d0 + d1 * d1; rq1 += d2 * d2 + d3 * d3;
            } else {
                if (mode == 2) {
                    d0 = expf(d0 - 64.f); d1 = expf(d1 - 64.f);
                    d2 = expf(d2 - 64.f); d3 = expf(d3 - 64.f);
                    rs0 += d0 + d1;
                    rs1 += d2 + d3;
                }
                uint16_t* base = (uint16_t*)Cout + (size_t)bz * sC;
                uint32_t lp0, lp1;
                uint32_t hp0 = packsplit2<FO>(d0, d1, lp0);
                uint32_t hp1 = packsplit2<FO>(d2, d3, lp1);
                uint16_t* r0p = base + (size_t)row0 * ldc + col;
                uint16_t* r1p = base + (size_t)row1 * ldc + col;
                *(uint32_t*)(r0p)     = hp0;
                *(uint32_t*)(r0p + J) = lp0;
                *(uint32_t*)(r1p)     = hp1;
                *(uint32_t*)(r1p + J) = lp1;
            }
        }
        if (mode == 2) {
            rs0 += __shfl_xor_sync(0xFFFFFFFFu, rs0, 1);
            rs0 += __shfl_xor_sync(0xFFFFFFFFu, rs0, 2);
            rs1 += __shfl_xor_sync(0xFFFFFFFFu, rs1, 1);
            rs1 += __shfl_xor_sync(0xFFFFFFFFu, rs1, 2);
            if (t == 0) {
                atomicAdd(&lsm[wm * 32 + mt * 16 + g], rs0);
                atomicAdd(&lsm[wm * 32 + mt * 16 + g + 8], rs1);
            }
        } else if (mode == 4) {
            rs0 += __shfl_xor_sync(0xFFFFFFFFu, rs0, 1);
            rs0 += __shfl_xor_sync(0xFFFFFFFFu, rs0, 2);
            rs1 += __shfl_xor_sync(0xFFFFFFFFu, rs1, 1);
            rs1 += __shfl_xor_sync(0xFFFFFFFFu, rs1, 2);
            rq0 += __shfl_xor_sync(0xFFFFFFFFu, rq0, 1);
            rq0 += __shfl_xor_sync(0xFFFFFFFFu, rq0, 2);
            rq1 += __shfl_xor_sync(0xFFFFFFFFu, rq1, 1);
            rq1 += __shfl_xor_sync(0xFFFFFFFFu, rq1, 2);
            if (t == 0) {
                int r0 = wm * 32 + mt * 16 + g, r1 = r0 + 8;
                atomicAdd(&s_ch[r0], (ull)(long long)llrintf(rs0 * (float)SC1));
                atomicAdd(&s_ch[r1], (ull)(long long)llrintf(rs1 * (float)SC1));
                atomicAdd(&s_ch[128 + r0], (ull)(long long)llrintf(rq0 * (float)SC2));
                atomicAdd(&s_ch[128 + r1], (ull)(long long)llrintf(rq1 * (float)SC2));
            }
        }
    }

    if (mode == 2) {
        __syncthreads();
        if (tid < 128)
            laux[((size_t)bz * N_ + m0 + tid) * 16 + blockIdx.x] = lsm[tid];
    } else if (mode == 4) {
        __syncthreads();
        if (tid < 128) {
            atomicAdd(&d_bnsum [m0 + tid], s_ch[tid]);
            atomicAdd(&d_bnsum2[m0 + tid], s_ch[128 + tid]);
        }
    }
}

// ---------------- normalize: P[r][m] = (E_hi + E_lo)[r][m] / l[r] as fp16 ----------------
// One block per row (2048 elems, 256 threads x 8).
__global__ void normalize_kernel(const __nv_bfloat16* __restrict__ E,
                                 const float* __restrict__ lp,
                                 __half* __restrict__ Pout)
{
    const size_t r = blockIdx.x;
    const int tid = threadIdx.x;
    const float* lrow = lp + r * 16;
    float l = 0.f;
#pragma unroll
    for (int j = 0; j < 16; j++) l += lrow[j];
    const float inv = 1.f / l;

    const __nv_bfloat16* eh = E + r * (2 * N_);
    const __nv_bfloat16* el = eh + N_;
    __half* po = Pout + r * N_;

    uint4 hv = ((const uint4*)eh)[tid];
    uint4 lv = ((const uint4*)el)[tid];
    const ushort* hp = (const ushort*)&hv;
    const ushort* lq = (const ushort*)&lv;
    uint4 ov;
    ushort* op = (ushort*)&ov;
#pragma unroll
    for (int i = 0; i < 8; i++) {
        float v = (__bfloat162float(__ushort_as_bfloat16(hp[i])) +
                   __bfloat162float(__ushort_as_bfloat16(lq[i]))) * inv;
        op[i] = __half_as_ushort(__float2half(v));
    }
    ((uint4*)po)[tid] = ov;
}

// ---------------- BN scale/shift from fixed-point sums ----------------
__global__ void bn_stats2_kernel(const float* __restrict__ gamma,
                                 const float* __restrict__ beta,
                                 float* __restrict__ scale,
                                 float* __restrict__ shift)
{
    int c = blockIdx.x * blockDim.x + threadIdx.x;
    if (c >= C_) return;
    const double M = (double)(B_ * N_);
    double mean = (double)(long long)d_bnsum[c]  / SC1 / M;
    double ms   = (double)(long long)d_bnsum2[c] / SC2 / M;
    double var  = ms - mean * mean;
    double inv  = 1.0 / sqrt(var + 1e-5);
    double sc   = (double)gamma[c] * inv;
    scale[c] = (float)sc;
    shift[c] = (float)((double)beta[c] - mean * sc);
}

// ---------------- finalize ----------------
__global__ void finalize_kernel(const float* __restrict__ zp,
                                const float* __restrict__ x,
                                const float* __restrict__ scale,
                                const float* __restrict__ shift,
                                float* __restrict__ out)
{
    const size_t idx4 = (size_t)blockIdx.x * blockDim.x + threadIdx.x;
    const size_t total4 = (size_t)B_ * C_ * N_ / 4;
    if (idx4 >= total4) return;
    const int nq = N_ / 4;
    int n4 = (int)(idx4 % nq);
    int c  = (int)((idx4 / nq) % C_);
    int b  = (int)(idx4 / ((size_t)nq * C_));

    float4 z = ((const float4*)zp)[(size_t)c * (B_ * N_ / 4) + (size_t)b * nq + n4];
    float4 xv = ((const float4*)x)[idx4];
    const float sc = scale[c], sh = shift[c];
    float4 o;
    o.x = z.x * sc + sh + xv.x;
    o.y = z.y * sc + sh + xv.y;
    o.z = z.z * sc + sh + xv.z;
    o.w = z.w * sc + sh + xv.w;
    ((float4*)out)[idx4] = o;
}

// ---------------- launch ----------------
template <typename T>
static T* sym_addr(const void* sym)
{
    void* p = nullptr;
    cudaGetSymbolAddress(&p, sym);
    return (T*)p;
}

extern "C" void kernel_launch(void* const* d_in, const int* in_sizes, int n_in,
                              void* d_out, int out_size)
{
    const float* x     = (const float*)d_in[0];
    const float* Wg    = (const float*)d_in[1];
    const float* Wth   = (const float*)d_in[2];
    const float* Wph   = (const float*)d_in[3];
    const float* Wz    = (const float*)d_in[4];
    const float* gamma = (const float*)d_in[5];
    const float* beta  = (const float*)d_in[6];
    float* out = (float*)d_out;

    __half*  xs  = sym_addr<__half>(d_xs);
    __half*  Wtp = sym_addr<__half>(d_Wtp);
    __half*  WgS = sym_addr<__half>(d_WgS);
    __half*  WzS = sym_addr<__half>(d_WzS);
    __half*  tp  = sym_addr<__half>(d_tp);
    __half*  gS  = sym_addr<__half>(d_gS);
    __half*  OS  = sym_addr<__half>(d_OS);
    __half*  P   = sym_addr<__half>(d_P);
    __nv_bfloat16* E = sym_addr<__nv_bfloat16>(d_E);
    float*   lp  = sym_addr<float>(d_lpar);
    float* zp    = sym_addr<float>(d_zp);
    float* scale = sym_addr<float>(d_scale);
    float* shift = sym_addr<float>(d_shift);

    cudaFuncSetAttribute(gemm_mma_kernel<1, 1>,
                         cudaFuncAttributeMaxDynamicSharedMemorySize, GEMM_SMEM);
    cudaFuncSetAttribute(gemm_mma_kernel<1, 0>,
                         cudaFuncAttributeMaxDynamicSharedMemorySize, GEMM_SMEM);

    // 1) weight splits (fp16 limbs) + zero bn accumulators
    split_all_kernel<<<dim3((P_ * C_ + 255) / 256, 4), 256>>>(
        Wth, Wph, Wg, Wz, Wtp, WgS, WzS);
    // 2) x transpose + split (fp16 limbs)
    xsplit_kernel<<<dim3(N_ / 32, C_ / 32, B_), dim3(32, 32)>>>(x, xs);

    // 3) theta+phi merged (fp16 in, fp16 limbs out), 3 terms: A lo on t2, B lo on t1
    gemm_mma_kernel<1, 1><<<dim3((2 * P_) / 128, N_ / 128, B_), 256, GEMM_SMEM>>>(
        (const uint16_t*)xs, 2 * C_, C_, (const uint16_t*)Wtp, 2 * C_, C_,
        tp, 4 * P_, C_, 1, 2 * P_, 3, 0b100, 0b010,
        (size_t)N_ * 2 * C_, 0, (size_t)N_ * 4 * P_, nullptr);
    // 4) g^T (fp16 in, fp16 limbs out), 1 term (hi x hi)
    gemm_mma_kernel<1, 1><<<dim3(N_ / 128, P_ / 128, B_), 256, GEMM_SMEM>>>(
        (const uint16_t*)WgS, 2 * C_, C_, (const uint16_t*)xs, 2 * C_, C_,
        gS, 2 * N_, C_, 1, N_, 1, 0, 0,
        0, (size_t)N_ * 2 * C_, (size_t)P_ * 2 * N_, nullptr);
    // 5) scores (fp16 in) -> E bf16 + row partial sums, 3 terms
    gemm_mma_kernel<1, 0><<<dim3(N_ / 128, N_ / 128, B_), 256, GEMM_SMEM>>>(
        (const uint16_t*)tp, 4 * P_, 2 * P_, (const uint16_t*)(tp + P_), 4 * P_, 2 * P_,
        E, 2 * N_, P_, 2, N_, 3, 0b100, 0b010,
        (size_t)N_ * 4 * P_, (size_t)N_ * 4 * P_, (size_t)N_ * 2 * N_, lp);
    // 6) normalize: P = (E_hi + E_lo) / l, fp16 single limb
    normalize_kernel<<<B_ * N_, 256>>>(E, lp, P);
    // 7) PV (fp16 in, fp16 limbs out): O = P x g, 2 terms (P*g_hi, P*g_lo)
    gemm_mma_kernel<1, 1><<<dim3(P_ / 128, N_ / 128, B_), 256, GEMM_SMEM>>>(
        (const uint16_t*)P, N_, 0, (const uint16_t*)gS, 2 * N_, N_,
        OS, 2 * P_, N_, 1, P_, 2, 0, 0b010,
        (size_t)N_ * N_, (size_t)P_ * 2 * N_, (size_t)N_ * 2 * P_, nullptr);
    // 8) z (fp16 in) fp32 out + fused BN channel sums, 1 term
    gemm_mma_kernel<1, 0><<<dim3((B_ * N_) / 128, C_ / 128, 1), 256, GEMM_SMEM>>>(
        (const uint16_t*)WzS, 2 * P_, P_, (const uint16_t*)OS, 2 * P_, P_,
        zp, B_ * N_, P_, 4, 0, 1, 0, 0,
        0, 0, 0, nullptr);
    // 9) BN scale/shift
    bn_stats2_kernel<<<2, 256>>>(gamma, beta, scale, shift);
    // 10) finalize
    {
        const int total4 = B_ * C_ * N_ / 4;
        finalize_kernel<<<(total4 + 255) / 256, 256>>>(zp, x, scale, shift, out);
    }
}

// round 15
// speedup vs baseline: 1.6842x; 1.1176x over previous
#include <cuda_runtime.h>
#include <cuda_bf16.h>
#include <cuda_fp16.h>
#include <math.h>
#include <stdint.h>

// Problem constants
#define B_ 8
#define C_ 512
#define N_ 2048
#define P_ 256

typedef unsigned long long ull;

// ---------------- scratch ----------------
// fp16 limb buffers
__device__ __half d_xs [(size_t)B_ * N_ * 2 * C_];  // x^T split [b][n][hi(C)|lo(C)]
__device__ __half d_Wtp[(2 * P_) * 2 * C_];         // rows: th(0..255), ph(256..511)
__device__ __half d_WgS[P_ * 2 * C_];
__device__ __half d_WzS[C_ * 2 * P_];
__device__ __half d_tp [(size_t)B_ * N_ * 4 * P_];  // [b][n][hi(2P)|lo(2P)]
__device__ __half d_gS [(size_t)B_ * P_ * 2 * N_];  // g^T [b][p][hi(N)|unused]
__device__ __half d_OS [(size_t)B_ * N_ * 2 * P_];
__device__ __half d_P  [(size_t)B_ * N_ * N_];      // normalized probs fp16 (single limb)
// bf16 buffers (E needs bf16 range pre-normalization)
__device__ __nv_bfloat16 d_E [(size_t)B_ * N_ * 2 * N_]; // exp(S-64) split
__device__ float d_lpar[(size_t)B_ * N_ * 16];           // per-jtile row sums
__device__ float d_zp[(size_t)C_ * B_ * N_];             // z channel-major [C][B*N]
__device__ ull  d_bnsum [C_];
__device__ ull  d_bnsum2[C_];
__device__ float d_scale[C_];
__device__ float d_shift[C_];

#define SC1 4194304.0   // 2^22 for sum(z)
#define SC2 65536.0     // 2^16 for sum(z^2)

// ---------------- helpers ----------------
__device__ __forceinline__ uint32_t smem_to_u32(const void* p) {
    uint32_t a;
    asm("{ .reg .u64 t; cvta.to.shared.u64 t, %1; cvt.u32.u64 %0, t; }" : "=r"(a) : "l"(p));
    return a;
}
__device__ __forceinline__ void split2h(float v, __half& h, __half& l) {
    h = __float2half(v);
    l = __float2half(v - __half2float(h));
}
// pack split pair; FO=1 -> fp16 limbs, FO=0 -> bf16 limbs
template <int FO>
__device__ __forceinline__ uint32_t packsplit2(float a, float b, uint32_t& lo) {
    if (FO) {
        __half h0, l0, h1, l1;
        split2h(a, h0, l0); split2h(b, h1, l1);
        lo = (uint32_t)__half_as_ushort(l0) | ((uint32_t)__half_as_ushort(l1) << 16);
        return (uint32_t)__half_as_ushort(h0) | ((uint32_t)__half_as_ushort(h1) << 16);
    } else {
        __nv_bfloat16 h0 = __float2bfloat16(a);
        __nv_bfloat16 l0 = __float2bfloat16(a - __bfloat162float(h0));
        __nv_bfloat16 h1 = __float2bfloat16(b);
        __nv_bfloat16 l1 = __float2bfloat16(b - __bfloat162float(h1));
        lo = (uint32_t)__bfloat16_as_ushort(l0) | ((uint32_t)__bfloat16_as_ushort(l1) << 16);
        return (uint32_t)__bfloat16_as_ushort(h0) | ((uint32_t)__bfloat16_as_ushort(h1) << 16);
    }
}

// ---------------- weight splits (one launch) ----------------
__global__ void split_all_kernel(const float* __restrict__ Wth, const float* __restrict__ Wph,
                                 const float* __restrict__ Wg,  const float* __restrict__ Wz,
                                 __half* __restrict__ Wtp,
                                 __half* __restrict__ WgS, __half* __restrict__ WzS)
{
    const int which = blockIdx.y;
    const int idx = blockIdx.x * blockDim.x + threadIdx.x;
    if (idx >= P_ * C_) return;
    const float* in;
    __half* out;
    int K, rofs = 0;
    if      (which == 0) { in = Wth; out = Wtp; K = C_; }
    else if (which == 1) { in = Wph; out = Wtp; K = C_; rofs = P_; }
    else if (which == 2) { in = Wg;  out = WgS; K = C_; }
    else                 { in = Wz;  out = WzS; K = P_;
                           if (idx < C_) { d_bnsum[idx] = 0ull; d_bnsum2[idx] = 0ull; } }
    int r = idx / K, k = idx % K;
    __half h, l;
    split2h(in[idx], h, l);
    __half* o = out + (size_t)(r + rofs) * (2 * K);
    o[k] = h;
    o[K + k] = l;
}

// ---------------- x transpose + split (fp16) ----------------
__global__ void xsplit_kernel(const float* __restrict__ x,
                              __half* __restrict__ xs)
{
    __shared__ float t[32][33];
    const int b = blockIdx.z;
    const int n0 = blockIdx.x * 32, c0 = blockIdx.y * 32;
    const int tx = threadIdx.x, ty = threadIdx.y;
    const float* xb = x + (size_t)b * C_ * N_;
    t[ty][tx] = xb[(size_t)(c0 + ty) * N_ + n0 + tx];
    __syncthreads();
    float v = t[tx][ty];
    int n = n0 + ty, c = c0 + tx;
    __half h, l;
    split2h(v, h, l);
    size_t row = ((size_t)b * N_ + n) * (size_t)(2 * C_);
    xs[row + c] = h;
    xs[row + C_ + c] = l;
}

// ---------------- mma.sync split GEMM ----------------
// C[i,j] = sum over nterms t of sum_k A[i, aoff(t)+k] * B[j, boff(t)+k], k in [0,K)
//   aoff(t) = (aMask>>t & 1) ? hlA : 0 ; boff(t) = (bMask>>t & 1) ? hlB : 0
// FI: 1 = fp16 operands, 0 = bf16 operands. FO: limb type for split outputs.
// mode: 1 = split [hi|lo] out (J==0 -> hi only); 2 = exp(acc-64) split + row sums;
//       4 = fp32 out + BN channel sums.
#define CH 64
#define PAD 72
#define STG_ELEMS (128 * PAD)
#define GEMM_SMEM (6 * STG_ELEMS * 2)

#define LDSM4(d, addr) \
    asm volatile("ldmatrix.sync.aligned.m8n8.x4.shared.b16 {%0,%1,%2,%3}, [%4];" \
        : "=r"((d)[0]), "=r"((d)[1]), "=r"((d)[2]), "=r"((d)[3]) : "r"(addr))

template <int FI>
__device__ __forceinline__ void mma16816(float ac[4], const uint32_t a[4],
                                         uint32_t b0, uint32_t b1) {
    if (FI) {
        asm volatile("mma.sync.aligned.m16n8k16.row.col.f32.f16.f16.f32 "
            "{%0,%1,%2,%3}, {%4,%5,%6,%7}, {%8,%9}, {%0,%1,%2,%3};"
            : "+f"(ac[0]), "+f"(ac[1]), "+f"(ac[2]), "+f"(ac[3])
            : "r"(a[0]), "r"(a[1]), "r"(a[2]), "r"(a[3]), "r"(b0), "r"(b1));
    } else {
        asm volatile("mma.sync.aligned.m16n8k16.row.col.f32.bf16.bf16.f32 "
            "{%0,%1,%2,%3}, {%4,%5,%6,%7}, {%8,%9}, {%0,%1,%2,%3};"
            : "+f"(ac[0]), "+f"(ac[1]), "+f"(ac[2]), "+f"(ac[3])
            : "r"(a[0]), "r"(a[1]), "r"(a[2]), "r"(a[3]), "r"(b0), "r"(b1));
    }
}

template <int FI, int FO>
__global__ void __launch_bounds__(256, 2) gemm_mma_kernel(
    const uint16_t* __restrict__ A, int lda, int hlA,
    const uint16_t* __restrict__ Bp, int ldb, int hlB,
    void* __restrict__ Cout, int ldc, int K, int mode, int J,
    int nterms, int aMask, int bMask,
    size_t sA, size_t sB, size_t sC, float* __restrict__ laux)
{
    extern __shared__ uint16_t sm[];
    __shared__ ull s_ch[256];
    const uint32_t smu = smem_to_u32(sm);

    const int tid  = threadIdx.x;
    const int wid  = tid >> 5;
    const int lane = tid & 31;
    const int wm = wid & 3;
    const int wn = wid >> 2;
    const int bz = blockIdx.z;
    A  += (size_t)bz * sA;
    Bp += (size_t)bz * sB;
    const int m0 = blockIdx.y * 128;
    const int j0 = blockIdx.x * 128;

    if (mode == 4 && tid < 256) s_ch[tid] = 0ull;

    float acc[2][8][4];
#pragma unroll
    for (int mt = 0; mt < 2; mt++)
#pragma unroll
        for (int nb = 0; nb < 8; nb++)
#pragma unroll
            for (int q = 0; q < 4; q++) acc[mt][nb][q] = 0.f;

    const int KC = K / CH;
    const int NC = nterms * KC;

    auto issue_chunk = [&](int aOff, int bOff, int buf) {
        const uint32_t aBase = smu + (uint32_t)(2 * buf) * STG_ELEMS * 2;
        const uint32_t bBase = smu + (uint32_t)(2 * buf + 1) * STG_ELEMS * 2;
#pragma unroll
        for (int i = 0; i < 4; i++) {
            int lin = tid + i * 256;
            int r  = lin >> 3;
            int c8 = lin & 7;
            const uint16_t* gA = A  + (size_t)(m0 + r) * lda + aOff + c8 * 8;
            const uint16_t* gB = Bp + (size_t)(j0 + r) * ldb + bOff + c8 * 8;
            uint32_t sa = aBase + (uint32_t)(r * PAD + c8 * 8) * 2;
            uint32_t sb = bBase + (uint32_t)(r * PAD + c8 * 8) * 2;
            asm volatile("cp.async.cg.shared.global [%0], [%1], 16;" :: "r"(sa), "l"(gA));
            asm volatile("cp.async.cg.shared.global [%0], [%1], 16;" :: "r"(sb), "l"(gB));
        }
        asm volatile("cp.async.commit_group;" ::: "memory");
    };

    // chunks 0,1 are always in term 0 (KC >= 4 for all our shapes); term 0 = hi/hi
    issue_chunk(0, 0, 0);
    issue_chunk(CH, CH, 1);

    int pf_t = 0, pf_off = 2 * CH;
    if (pf_off >= K) { pf_off -= K; pf_t++; }

    const int lrow = lane & 15;
    const int kun  = lane >> 4;
    const uint32_t aRowOff = (uint32_t)((wm * 32 + lrow) * PAD + kun * 8) * 2;
    const uint32_t bRowOff = (uint32_t)((wn * 64 + lrow) * PAD + kun * 8) * 2;

    int buf = 0;
    for (int c = 0; c < NC; c++) {
        if (c + 1 < NC) asm volatile("cp.async.wait_group 1;" ::: "memory");
        else            asm volatile("cp.async.wait_group 0;" ::: "memory");
        __syncthreads();
        if (c + 2 < NC) {
            int aOff = pf_off + (((aMask >> pf_t) & 1) ? hlA : 0);
            int bOff = pf_off + (((bMask >> pf_t) & 1) ? hlB : 0);
            issue_chunk(aOff, bOff, (buf + 2) % 3);
            pf_off += CH;
            if (pf_off == K) { pf_off = 0; pf_t++; }
        }

        const uint32_t aBase = smu + (uint32_t)(2 * buf) * STG_ELEMS * 2 + aRowOff;
        const uint32_t bBase = smu + (uint32_t)(2 * buf + 1) * STG_ELEMS * 2 + bRowOff;

        uint32_t af[2][2][4];
        uint32_t bg[2][4];

        LDSM4(af[0][0], aBase);
        LDSM4(af[0][1], aBase + 16 * PAD * 2);

#pragma unroll
        for (int ks = 0; ks < 4; ks++) {
            const int cur = ks & 1, nxt = cur ^ 1;
            const uint32_t kOff = (uint32_t)(ks * 32);
            LDSM4(bg[0], bBase + kOff);
#pragma unroll
            for (int nb2 = 0; nb2 < 4; nb2++) {
                const int gc = nb2 & 1, gn = gc ^ 1;
                if (nb2 < 3) {
                    LDSM4(bg[gn], bBase + kOff + (uint32_t)((nb2 + 1) * 16 * PAD * 2));
                } else if (ks < 3) {
                    LDSM4(af[nxt][0], aBase + kOff + 32);
                    LDSM4(af[nxt][1], aBase + kOff + 32 + 16 * PAD * 2);
                }
#pragma unroll
                for (int mt = 0; mt < 2; mt++) {
                    mma16816<FI>(acc[mt][nb2 * 2],     af[cur][mt], bg[gc][0], bg[gc][2]);
                    mma16816<FI>(acc[mt][nb2 * 2 + 1], af[cur][mt], bg[gc][1], bg[gc][3]);
                }
            }
        }
        buf = (buf + 1) % 3;
    }

    // ---------------- epilogue ----------------
    const int g = lane >> 2;
    const int t = lane & 3;
    float* lsm = (float*)sm;

    if (mode == 2) {
        __syncthreads();
        if (tid < 128) lsm[tid] = 0.f;
        __syncthreads();
    }

#pragma unroll
    for (int mt = 0; mt < 2; mt++) {
        const int row0 = m0 + wm * 32 + mt * 16 + g;
        const int row1 = row0 + 8;
        float rs0 = 0.f, rs1 = 0.f, rq0 = 0.f, rq1 = 0.f;
#pragma unroll
        for (int nb = 0; nb < 8; nb++) {
            const int col = j0 + wn * 64 + nb * 8 + t * 2;
            float d0 = acc[mt][nb][0], d1 = acc[mt][nb][1];
            float d2 = acc[mt][nb][2], d3 = acc[mt][nb][3];
            if (mode == 4) {
                float* base = (float*)Cout + (size_t)bz * sC;
                *(float2*)(base + (size_t)row0 * ldc + col) = make_float2(d0, d1);
                *(float2*)(base + (size_t)row1 * ldc + col) = make_float2(d2, d3);
                rs0 += d0 + d1; rs1 += d2 + d3;
                rq0 += d0 * d0 + d1 * d1; rq1 += d2 * d2 + d3 * d3;
            } else {
                if (mode == 2) {
                    d0 = expf(d0 - 64.f); d1 = expf(d1 - 64.f);
                    d2 = expf(d2 - 64.f); d3 = expf(d3 - 64.f);
                    rs0 += d0 + d1;
                    rs1 += d2 + d3;
                }
                uint16_t* base = (uint16_t*)Cout + (size_t)bz * sC;
                uint32_t lp0, lp1;
                uint32_t hp0 = packsplit2<FO>(d0, d1, lp0);
                uint32_t hp1 = packsplit2<FO>(d2, d3, lp1);
                uint16_t* r0p = base + (size_t)row0 * ldc + col;
                uint16_t* r1p = base + (size_t)row1 * ldc + col;
                *(uint32_t*)(r0p) = hp0;
                *(uint32_t*)(r1p) = hp1;
                if (J) {
                    *(uint32_t*)(r0p + J) = lp0;
                    *(uint32_t*)(r1p + J) = lp1;
                }
            }
        }
        if (mode == 2) {
            rs0 += __shfl_xor_sync(0xFFFFFFFFu, rs0, 1);
            rs0 += __shfl_xor_sync(0xFFFFFFFFu, rs0, 2);
            rs1 += __shfl_xor_sync(0xFFFFFFFFu, rs1, 1);
            rs1 += __shfl_xor_sync(0xFFFFFFFFu, rs1, 2);
            if (t == 0) {
                atomicAdd(&lsm[wm * 32 + mt * 16 + g], rs0);
                atomicAdd(&lsm[wm * 32 + mt * 16 + g + 8], rs1);
            }
        } else if (mode == 4) {
            rs0 += __shfl_xor_sync(0xFFFFFFFFu, rs0, 1);
            rs0 += __shfl_xor_sync(0xFFFFFFFFu, rs0, 2);
            rs1 += __shfl_xor_sync(0xFFFFFFFFu, rs1, 1);
            rs1 += __shfl_xor_sync(0xFFFFFFFFu, rs1, 2);
            rq0 += __shfl_xor_sync(0xFFFFFFFFu, rq0, 1);
            rq0 += __shfl_xor_sync(0xFFFFFFFFu, rq0, 2);
            rq1 += __shfl_xor_sync(0xFFFFFFFFu, rq1, 1);
            rq1 += __shfl_xor_sync(0xFFFFFFFFu, rq1, 2);
            if (t == 0) {
                int r0 = wm * 32 + mt * 16 + g, r1 = r0 + 8;
                atomicAdd(&s_ch[r0], (ull)(long long)llrintf(rs0 * (float)SC1));
                atomicAdd(&s_ch[r1], (ull)(long long)llrintf(rs1 * (float)SC1));
                atomicAdd(&s_ch[128 + r0], (ull)(long long)llrintf(rq0 * (float)SC2));
                atomicAdd(&s_ch[128 + r1], (ull)(long long)llrintf(rq1 * (float)SC2));
            }
        }
    }

    if (mode == 2) {
        __syncthreads();
        if (tid < 128)
            laux[((size_t)bz * N_ + m0 + tid) * 16 + blockIdx.x] = lsm[tid];
    } else if (mode == 4) {
        __syncthreads();
        if (tid < 128) {
            atomicAdd(&d_bnsum [m0 + tid], s_ch[tid]);
            atomicAdd(&d_bnsum2[m0 + tid], s_ch[128 + tid]);
        }
    }
}

// ---------------- normalize: P[r][m] = (E_hi + E_lo)[r][m] / l[r] as fp16 ----------------
__global__ void normalize_kernel(const __nv_bfloat16* __restrict__ E,
                                 const float* __restrict__ lp,
                                 __half* __restrict__ Pout)
{
    const size_t r = blockIdx.x;
    const int tid = threadIdx.x;
    const float* lrow = lp + r * 16;
    float l = 0.f;
#pragma unroll
    for (int j = 0; j < 16; j++) l += lrow[j];
    const float inv = 1.f / l;

    const __nv_bfloat16* eh = E + r * (2 * N_);
    const __nv_bfloat16* el = eh + N_;
    __half* po = Pout + r * N_;

    uint4 hv = ((const uint4*)eh)[tid];
    uint4 lv = ((const uint4*)el)[tid];
    const ushort* hp = (const ushort*)&hv;
    const ushort* lq = (const ushort*)&lv;
    uint4 ov;
    ushort* op = (ushort*)&ov;
#pragma unroll
    for (int i = 0; i < 8; i++) {
        float v = (__bfloat162float(__ushort_as_bfloat16(hp[i])) +
                   __bfloat162float(__ushort_as_bfloat16(lq[i]))) * inv;
        op[i] = __half_as_ushort(__float2half(v));
    }
    ((uint4*)po)[tid] = ov;
}

// ---------------- BN scale/shift from fixed-point sums ----------------
__global__ void bn_stats2_kernel(const float* __restrict__ gamma,
                                 const float* __restrict__ beta,
                                 float* __restrict__ scale,
                                 float* __restrict__ shift)
{
    int c = blockIdx.x * blockDim.x + threadIdx.x;
    if (c >= C_) return;
    const double M = (double)(B_ * N_);
    double mean = (double)(long long)d_bnsum[c]  / SC1 / M;
    double ms   = (double)(long long)d_bnsum2[c] / SC2 / M;
    double var  = ms - mean * mean;
    double inv  = 1.0 / sqrt(var + 1e-5);
    double sc   = (double)gamma[c] * inv;
    scale[c] = (float)sc;
    shift[c] = (float)((double)beta[c] - mean * sc);
}

// ---------------- finalize ----------------
__global__ void finalize_kernel(const float* __restrict__ zp,
                                const float* __restrict__ x,
                                const float* __restrict__ scale,
                                const float* __restrict__ shift,
                                float* __restrict__ out)
{
    const size_t idx4 = (size_t)blockIdx.x * blockDim.x + threadIdx.x;
    const size_t total4 = (size_t)B_ * C_ * N_ / 4;
    if (idx4 >= total4) return;
    const int nq = N_ / 4;
    int n4 = (int)(idx4 % nq);
    int c  = (int)((idx4 / nq) % C_);
    int b  = (int)(idx4 / ((size_t)nq * C_));

    float4 z = ((const float4*)zp)[(size_t)c * (B_ * N_ / 4) + (size_t)b * nq + n4];
    float4 xv = ((const float4*)x)[idx4];
    const float sc = scale[c], sh = shift[c];
    float4 o;
    o.x = z.x * sc + sh + xv.x;
    o.y = z.y * sc + sh + xv.y;
    o.z = z.z * sc + sh + xv.z;
    o.w = z.w * sc + sh + xv.w;
    ((float4*)out)[idx4] = o;
}

// ---------------- launch ----------------
template <typename T>
static T* sym_addr(const void* sym)
{
    void* p = nullptr;
    cudaGetSymbolAddress(&p, sym);
    return (T*)p;
}

extern "C" void kernel_launch(void* const* d_in, const int* in_sizes, int n_in,
                              void* d_out, int out_size)
{
    const float* x     = (const float*)d_in[0];
    const float* Wg    = (const float*)d_in[1];
    const float* Wth   = (const float*)d_in[2];
    const float* Wph   = (const float*)d_in[3];
    const float* Wz    = (const float*)d_in[4];
    const float* gamma = (const float*)d_in[5];
    const float* beta  = (const float*)d_in[6];
    float* out = (float*)d_out;

    __half*  xs  = sym_addr<__half>(d_xs);
    __half*  Wtp = sym_addr<__half>(d_Wtp);
    __half*  WgS = sym_addr<__half>(d_WgS);
    __half*  WzS = sym_addr<__half>(d_WzS);
    __half*  tp  = sym_addr<__half>(d_tp);
    __half*  gS  = sym_addr<__half>(d_gS);
    __half*  OS  = sym_addr<__half>(d_OS);
    __half*  P   = sym_addr<__half>(d_P);
    __nv_bfloat16* E = sym_addr<__nv_bfloat16>(d_E);
    float*   lp  = sym_addr<float>(d_lpar);
    float* zp    = sym_addr<float>(d_zp);
    float* scale = sym_addr<float>(d_scale);
    float* shift = sym_addr<float>(d_shift);

    cudaFuncSetAttribute(gemm_mma_kernel<1, 1>,
                         cudaFuncAttributeMaxDynamicSharedMemorySize, GEMM_SMEM);
    cudaFuncSetAttribute(gemm_mma_kernel<1, 0>,
                         cudaFuncAttributeMaxDynamicSharedMemorySize, GEMM_SMEM);

    // 1) weight splits (fp16 limbs) + zero bn accumulators
    split_all_kernel<<<dim3((P_ * C_ + 255) / 256, 4), 256>>>(
        Wth, Wph, Wg, Wz, Wtp, WgS, WzS);
    // 2) x transpose + split (fp16 limbs)
    xsplit_kernel<<<dim3(N_ / 32, C_ / 32, B_), dim3(32, 32)>>>(x, xs);

    // 3) theta+phi merged (fp16 in, fp16 limbs out), 3 terms
    gemm_mma_kernel<1, 1><<<dim3((2 * P_) / 128, N_ / 128, B_), 256, GEMM_SMEM>>>(
        (const uint16_t*)xs, 2 * C_, C_, (const uint16_t*)Wtp, 2 * C_, C_,
        tp, 4 * P_, C_, 1, 2 * P_, 3, 0b100, 0b010,
        (size_t)N_ * 2 * C_, 0, (size_t)N_ * 4 * P_, nullptr);
    // 4) g^T (fp16 in, fp16 single-limb out), 1 term (hi x hi)
    gemm_mma_kernel<1, 1><<<dim3(N_ / 128, P_ / 128, B_), 256, GEMM_SMEM>>>(
        (const uint16_t*)WgS, 2 * C_, C_, (const uint16_t*)xs, 2 * C_, C_,
        gS, 2 * N_, C_, 1, 0 /*J=0: hi only*/, 1, 0, 0,
        0, (size_t)N_ * 2 * C_, (size_t)P_ * 2 * N_, nullptr);
    // 5) scores (fp16 in) -> E bf16 + row partial sums, 3 terms
    gemm_mma_kernel<1, 0><<<dim3(N_ / 128, N_ / 128, B_), 256, GEMM_SMEM>>>(
        (const uint16_t*)tp, 4 * P_, 2 * P_, (const uint16_t*)(tp + P_), 4 * P_, 2 * P_,
        E, 2 * N_, P_, 2, N_, 3, 0b100, 0b010,
        (size_t)N_ * 4 * P_, (size_t)N_ * 4 * P_, (size_t)N_ * 2 * N_, lp);
    // 6) normalize: P = (E_hi + E_lo) / l, fp16 single limb
    normalize_kernel<<<B_ * N_, 256>>>(E, lp, P);
    // 7) PV (fp16 in, fp16 limbs out): O = P x g_hi, 1 term
    gemm_mma_kernel<1, 1><<<dim3(P_ / 128, N_ / 128, B_), 256, GEMM_SMEM>>>(
        (const uint16_t*)P, N_, 0, (const uint16_t*)gS, 2 * N_, N_,
        OS, 2 * P_, N_, 1, P_, 1, 0, 0,
        (size_t)N_ * N_, (size_t)P_ * 2 * N_, (size_t)N_ * 2 * P_, nullptr);
    // 8) z (fp16 in) fp32 out + fused BN channel sums, 1 term
    gemm_mma_kernel<1, 0><<<dim3((B_ * N_) / 128, C_ / 128, 1), 256, GEMM_SMEM>>>(
        (const uint16_t*)WzS, 2 * P_, P_, (const uint16_t*)OS, 2 * P_, P_,
        zp, B_ * N_, P_, 4, 0, 1, 0, 0,
        0, 0, 0, nullptr);
    // 9) BN scale/shift
    bn_stats2_kernel<<<2, 256>>>(gamma, beta, scale, shift);
    // 10) finalize
    {
        const int total4 = B_ * C_ * N_ / 4;
        finalize_kernel<<<(total4 + 255) / 256, 256>>>(zp, x, scale, shift, out);
    }
}

// round 17
// speedup vs baseline: 1.6923x; 1.0048x over previous
#include <cuda_runtime.h>
#include <cuda_bf16.h>
#include <cuda_fp16.h>
#include <math.h>
#include <stdint.h>

// Problem constants
#define B_ 8
#define C_ 512
#define N_ 2048
#define P_ 256

typedef unsigned long long ull;

// ---------------- scratch ----------------
// fp16 limb buffers
__device__ __half d_xs [(size_t)B_ * N_ * 2 * C_];  // x^T split [b][n][hi(C)|lo(C)]
__device__ __half d_Wtp[(2 * P_) * 2 * C_];         // rows: th(0..255), ph(256..511)
__device__ __half d_WgS[P_ * 2 * C_];
__device__ __half d_WzS[C_ * 2 * P_];
__device__ __half d_tp [(size_t)B_ * N_ * 4 * P_];  // [b][n][hi(2P)|lo(2P)]
__device__ __half d_gS [(size_t)B_ * P_ * 2 * N_];  // g^T [b][p][hi(N)|unused]
__device__ __half d_OS [(size_t)B_ * N_ * P_];      // [b][n][hi(P)] compact
__device__ __half d_P  [(size_t)B_ * N_ * N_];      // normalized probs fp16 (single limb)
// bf16 buffers (E needs bf16 range pre-normalization)
__device__ __nv_bfloat16 d_E [(size_t)B_ * N_ * 2 * N_]; // exp(S-64) split
__device__ float d_lpar[(size_t)B_ * N_ * 16];           // per-jtile row sums
__device__ float d_zp[(size_t)C_ * B_ * N_];             // z channel-major [C][B*N]
__device__ ull  d_bnsum [C_];
__device__ ull  d_bnsum2[C_];
__device__ float d_scale[C_];
__device__ float d_shift[C_];

#define SC1 4194304.0   // 2^22 for sum(z)
#define SC2 65536.0     // 2^16 for sum(z^2)

// ---------------- helpers ----------------
__device__ __forceinline__ uint32_t smem_to_u32(const void* p) {
    uint32_t a;
    asm("{ .reg .u64 t; cvta.to.shared.u64 t, %1; cvt.u32.u64 %0, t; }" : "=r"(a) : "l"(p));
    return a;
}
__device__ __forceinline__ void split2h(float v, __half& h, __half& l) {
    h = __float2half(v);
    l = __float2half(v - __half2float(h));
}
// pack split pair; FO=1 -> fp16 limbs, FO=0 -> bf16 limbs
template <int FO>
__device__ __forceinline__ uint32_t packsplit2(float a, float b, uint32_t& lo) {
    if (FO) {
        __half h0, l0, h1, l1;
        split2h(a, h0, l0); split2h(b, h1, l1);
        lo = (uint32_t)__half_as_ushort(l0) | ((uint32_t)__half_as_ushort(l1) << 16);
        return (uint32_t)__half_as_ushort(h0) | ((uint32_t)__half_as_ushort(h1) << 16);
    } else {
        __nv_bfloat16 h0 = __float2bfloat16(a);
        __nv_bfloat16 l0 = __float2bfloat16(a - __bfloat162float(h0));
        __nv_bfloat16 h1 = __float2bfloat16(b);
        __nv_bfloat16 l1 = __float2bfloat16(b - __bfloat162float(h1));
        lo = (uint32_t)__bfloat16_as_ushort(l0) | ((uint32_t)__bfloat16_as_ushort(l1) << 16);
        return (uint32_t)__bfloat16_as_ushort(h0) | ((uint32_t)__bfloat16_as_ushort(h1) << 16);
    }
}

// ---------------- weight splits (one launch) ----------------
__global__ void split_all_kernel(const float* __restrict__ Wth, const float* __restrict__ Wph,
                                 const float* __restrict__ Wg,  const float* __restrict__ Wz,
                                 __half* __restrict__ Wtp,
                                 __half* __restrict__ WgS, __half* __restrict__ WzS)
{
    const int which = blockIdx.y;
    const int idx = blockIdx.x * blockDim.x + threadIdx.x;
    if (idx >= P_ * C_) return;
    const float* in;
    __half* out;
    int K, rofs = 0;
    if      (which == 0) { in = Wth; out = Wtp; K = C_; }
    else if (which == 1) { in = Wph; out = Wtp; K = C_; rofs = P_; }
    else if (which == 2) { in = Wg;  out = WgS; K = C_; }
    else                 { in = Wz;  out = WzS; K = P_;
                           if (idx < C_) { d_bnsum[idx] = 0ull; d_bnsum2[idx] = 0ull; } }
    int r = idx / K, k = idx % K;
    __half h, l;
    split2h(in[idx], h, l);
    __half* o = out + (size_t)(r + rofs) * (2 * K);
    o[k] = h;
    o[K + k] = l;
}

// ---------------- x transpose + split (fp16) ----------------
__global__ void xsplit_kernel(const float* __restrict__ x,
                              __half* __restrict__ xs)
{
    __shared__ float t[32][33];
    const int b = blockIdx.z;
    const int n0 = blockIdx.x * 32, c0 = blockIdx.y * 32;
    const int tx = threadIdx.x, ty = threadIdx.y;
    const float* xb = x + (size_t)b * C_ * N_;
    t[ty][tx] = xb[(size_t)(c0 + ty) * N_ + n0 + tx];
    __syncthreads();
    float v = t[tx][ty];
    int n = n0 + ty, c = c0 + tx;
    __half h, l;
    split2h(v, h, l);
    size_t row = ((size_t)b * N_ + n) * (size_t)(2 * C_);
    xs[row + c] = h;
    xs[row + C_ + c] = l;
}

// ---------------- mma.sync split GEMM ----------------
// C[i,j] = sum over nterms t of sum_k A[i, aoff(t)+k] * B[j, boff(t)+k], k in [0,K)
//   aoff(t) = (aMask>>t & 1) ? hlA : 0 ; boff(t) = (bMask>>t & 1) ? hlB : 0
// FI: 1 = fp16 operands, 0 = bf16 operands. FO: limb type for split outputs.
// mode: 1 = split out (J==0 -> hi only); 2 = exp(acc-64) split + row partial sums;
//       4 = fp32 out + BN channel sums.
#define CH 64
#define PAD 72
#define STG_ELEMS (128 * PAD)
#define GEMM_SMEM (6 * STG_ELEMS * 2)

#define LDSM4(d, addr) \
    asm volatile("ldmatrix.sync.aligned.m8n8.x4.shared.b16 {%0,%1,%2,%3}, [%4];" \
        : "=r"((d)[0]), "=r"((d)[1]), "=r"((d)[2]), "=r"((d)[3]) : "r"(addr))

template <int FI>
__device__ __forceinline__ void mma16816(float ac[4], const uint32_t a[4],
                                         uint32_t b0, uint32_t b1) {
    if (FI) {
        asm volatile("mma.sync.aligned.m16n8k16.row.col.f32.f16.f16.f32 "
            "{%0,%1,%2,%3}, {%4,%5,%6,%7}, {%8,%9}, {%0,%1,%2,%3};"
            : "+f"(ac[0]), "+f"(ac[1]), "+f"(ac[2]), "+f"(ac[3])
            : "r"(a[0]), "r"(a[1]), "r"(a[2]), "r"(a[3]), "r"(b0), "r"(b1));
    } else {
        asm volatile("mma.sync.aligned.m16n8k16.row.col.f32.bf16.bf16.f32 "
            "{%0,%1,%2,%3}, {%4,%5,%6,%7}, {%8,%9}, {%0,%1,%2,%3};"
            : "+f"(ac[0]), "+f"(ac[1]), "+f"(ac[2]), "+f"(ac[3])
            : "r"(a[0]), "r"(a[1]), "r"(a[2]), "r"(a[3]), "r"(b0), "r"(b1));
    }
}

template <int FI, int FO>
__global__ void __launch_bounds__(256, 2) gemm_mma_kernel(
    const uint16_t* __restrict__ A, int lda, int hlA,
    const uint16_t* __restrict__ Bp, int ldb, int hlB,
    void* __restrict__ Cout, int ldc, int K, int mode, int J,
    int nterms, int aMask, int bMask,
    size_t sA, size_t sB, size_t sC, float* __restrict__ laux)
{
    extern __shared__ uint16_t sm[];
    __shared__ ull s_ch[256];
    const uint32_t smu = smem_to_u32(sm);

    const int tid  = threadIdx.x;
    const int wid  = tid >> 5;
    const int lane = tid & 31;
    const int wm = wid & 3;
    const int wn = wid >> 2;
    const int bz = blockIdx.z;
    A  += (size_t)bz * sA;
    Bp += (size_t)bz * sB;
    const int m0 = blockIdx.y * 128;
    const int j0 = blockIdx.x * 128;

    if (mode == 4 && tid < 256) s_ch[tid] = 0ull;

    float acc[2][8][4];
#pragma unroll
    for (int mt = 0; mt < 2; mt++)
#pragma unroll
        for (int nb = 0; nb < 8; nb++)
#pragma unroll
            for (int q = 0; q < 4; q++) acc[mt][nb][q] = 0.f;

    const int KC = K / CH;
    const int NC = nterms * KC;

    auto issue_chunk = [&](int aOff, int bOff, int buf) {
        const uint32_t aBase = smu + (uint32_t)(2 * buf) * STG_ELEMS * 2;
        const uint32_t bBase = smu + (uint32_t)(2 * buf + 1) * STG_ELEMS * 2;
#pragma unroll
        for (int i = 0; i < 4; i++) {
            int lin = tid + i * 256;
            int r  = lin >> 3;
            int c8 = lin & 7;
            const uint16_t* gA = A  + (size_t)(m0 + r) * lda + aOff + c8 * 8;
            const uint16_t* gB = Bp + (size_t)(j0 + r) * ldb + bOff + c8 * 8;
            uint32_t sa = aBase + (uint32_t)(r * PAD + c8 * 8) * 2;
            uint32_t sb = bBase + (uint32_t)(r * PAD + c8 * 8) * 2;
            asm volatile("cp.async.cg.shared.global [%0], [%1], 16;" :: "r"(sa), "l"(gA));
            asm volatile("cp.async.cg.shared.global [%0], [%1], 16;" :: "r"(sb), "l"(gB));
        }
        asm volatile("cp.async.commit_group;" ::: "memory");
    };

    // chunks 0,1 are always in term 0 (KC >= 4 for all our shapes); term 0 = hi/hi
    issue_chunk(0, 0, 0);
    issue_chunk(CH, CH, 1);

    int pf_t = 0, pf_off = 2 * CH;
    if (pf_off >= K) { pf_off -= K; pf_t++; }

    const int lrow = lane & 15;
    const int kun  = lane >> 4;
    const uint32_t aRowOff = (uint32_t)((wm * 32 + lrow) * PAD + kun * 8) * 2;
    const uint32_t bRowOff = (uint32_t)((wn * 64 + lrow) * PAD + kun * 8) * 2;

    int buf = 0;
    for (int c = 0; c < NC; c++) {
        if (c + 1 < NC) asm volatile("cp.async.wait_group 1;" ::: "memory");
        else            asm volatile("cp.async.wait_group 0;" ::: "memory");
        __syncthreads();
        if (c + 2 < NC) {
            int aOff = pf_off + (((aMask >> pf_t) & 1) ? hlA : 0);
            int bOff = pf_off + (((bMask >> pf_t) & 1) ? hlB : 0);
            issue_chunk(aOff, bOff, (buf + 2) % 3);
            pf_off += CH;
            if (pf_off == K) { pf_off = 0; pf_t++; }
        }

        const uint32_t aBase = smu + (uint32_t)(2 * buf) * STG_ELEMS * 2 + aRowOff;
        const uint32_t bBase = smu + (uint32_t)(2 * buf + 1) * STG_ELEMS * 2 + bRowOff;

        uint32_t af[2][2][4];
        uint32_t bg[2][4];

        LDSM4(af[0][0], aBase);
        LDSM4(af[0][1], aBase + 16 * PAD * 2);

#pragma unroll
        for (int ks = 0; ks < 4; ks++) {
            const int cur = ks & 1, nxt = cur ^ 1;
            const uint32_t kOff = (uint32_t)(ks * 32);
            LDSM4(bg[0], bBase + kOff);
#pragma unroll
            for (int nb2 = 0; nb2 < 4; nb2++) {
                const int gc = nb2 & 1, gn = gc ^ 1;
                if (nb2 < 3) {
                    LDSM4(bg[gn], bBase + kOff + (uint32_t)((nb2 + 1) * 16 * PAD * 2));
                } else if (ks < 3) {
                    LDSM4(af[nxt][0], aBase + kOff + 32);
                    LDSM4(af[nxt][1], aBase + kOff + 32 + 16 * PAD * 2);
                }
#pragma unroll
                for (int mt = 0; mt < 2; mt++) {
                    mma16816<FI>(acc[mt][nb2 * 2],     af[cur][mt], bg[gc][0], bg[gc][2]);
                    mma16816<FI>(acc[mt][nb2 * 2 + 1], af[cur][mt], bg[gc][1], bg[gc][3]);
                }
            }
        }
        buf = (buf + 1) % 3;
    }

    // ---------------- epilogue ----------------
    const int g = lane >> 2;
    const int t = lane & 3;
    float* lsm = (float*)sm;

    if (mode == 2) {
        __syncthreads();
        if (tid < 128) lsm[tid] = 0.f;
        __syncthreads();
    }

#pragma unroll
    for (int mt = 0; mt < 2; mt++) {
        const int row0 = m0 + wm * 32 + mt * 16 + g;
        const int row1 = row0 + 8;
        float rs0 = 0.f, rs1 = 0.f, rq0 = 0.f, rq1 = 0.f;
#pragma unroll
        for (int nb = 0; nb < 8; nb++) {
            const int col = j0 + wn * 64 + nb * 8 + t * 2;
            float d0 = acc[mt][nb][0], d1 = acc[mt][nb][1];
            float d2 = acc[mt][nb][2], d3 = acc[mt][nb][3];
            if (mode == 4) {
                float* base = (float*)Cout + (size_t)bz * sC;
                *(float2*)(base + (size_t)row0 * ldc + col) = make_float2(d0, d1);
                *(float2*)(base + (size_t)row1 * ldc + col) = make_float2(d2, d3);
                rs0 += d0 + d1; rs1 += d2 + d3;
                rq0 += d0 * d0 + d1 * d1; rq1 += d2 * d2 + d3 * d3;
            } else {
                if (mode == 2) {
                    d0 = expf(d0 - 64.f); d1 = expf(d1 - 64.f);
                    d2 = expf(d2 - 64.f); d3 = expf(d3 - 64.f);
                    rs0 += d0 + d1;
                    rs1 += d2 + d3;
                }
                uint16_t* base = (uint16_t*)Cout + (size_t)bz * sC;
                uint32_t lp0, lp1;
                uint32_t hp0 = packsplit2<FO>(d0, d1, lp0);
                uint32_t hp1 = packsplit2<FO>(d2, d3, lp1);
                uint16_t* r0p = base + (size_t)row0 * ldc + col;
                uint16_t* r1p = base + (size_t)row1 * ldc + col;
                *(uint32_t*)(r0p) = hp0;
                *(uint32_t*)(r1p) = hp1;
                if (J) {
                    *(uint32_t*)(r0p + J) = lp0;
                    *(uint32_t*)(r1p + J) = lp1;
                }
            }
        }
        if (mode == 2) {
            rs0 += __shfl_xor_sync(0xFFFFFFFFu, rs0, 1);
            rs0 += __shfl_xor_sync(0xFFFFFFFFu, rs0, 2);
            rs1 += __shfl_xor_sync(0xFFFFFFFFu, rs1, 1);
            rs1 += __shfl_xor_sync(0xFFFFFFFFu, rs1, 2);
            if (t == 0) {
                atomicAdd(&lsm[wm * 32 + mt * 16 + g], rs0);
                atomicAdd(&lsm[wm * 32 + mt * 16 + g + 8], rs1);
            }
        } else if (mode == 4) {
            rs0 += __shfl_xor_sync(0xFFFFFFFFu, rs0, 1);
            rs0 += __shfl_xor_sync(0xFFFFFFFFu, rs0, 2);
            rs1 += __shfl_xor_sync(0xFFFFFFFFu, rs1, 1);
            rs1 += __shfl_xor_sync(0xFFFFFFFFu, rs1, 2);
            rq0 += __shfl_xor_sync(0xFFFFFFFFu, rq0, 1);
            rq0 += __shfl_xor_sync(0xFFFFFFFFu, rq0, 2);
            rq1 += __shfl_xor_sync(0xFFFFFFFFu, rq1, 1);
            rq1 += __shfl_xor_sync(0xFFFFFFFFu, rq1, 2);
            if (t == 0) {
                int r0 = wm * 32 + mt * 16 + g, r1 = r0 + 8;
                atomicAdd(&s_ch[r0], (ull)(long long)llrintf(rs0 * (float)SC1));
                atomicAdd(&s_ch[r1], (ull)(long long)llrintf(rs1 * (float)SC1));
                atomicAdd(&s_ch[128 + r0], (ull)(long long)llrintf(rq0 * (float)SC2));
                atomicAdd(&s_ch[128 + r1], (ull)(long long)llrintf(rq1 * (float)SC2));
            }
        }
    }

    if (mode == 2) {
        __syncthreads();
        if (tid < 128)
            laux[((size_t)bz * N_ + m0 + tid) * 16 + blockIdx.x] = lsm[tid];
    } else if (mode == 4) {
        __syncthreads();
        if (tid < 128) {
            atomicAdd(&d_bnsum [m0 + tid], s_ch[tid]);
            atomicAdd(&d_bnsum2[m0 + tid], s_ch[128 + tid]);
        }
    }
}

// ---------------- normalize: P[r][m] = (E_hi + E_lo)[r][m] / l[r] as fp16 ----------------
__global__ void normalize_kernel(const __nv_bfloat16* __restrict__ E,
                                 const float* __restrict__ lp,
                                 __half* __restrict__ Pout)
{
    const size_t r = blockIdx.x;
    const int tid = threadIdx.x;
    const float* lrow = lp + r * 16;
    float l = 0.f;
#pragma unroll
    for (int j = 0; j < 16; j++) l += lrow[j];
    const float inv = 1.f / l;

    const __nv_bfloat16* eh = E + r * (2 * N_);
    const __nv_bfloat16* el = eh + N_;
    __half* po = Pout + r * N_;

    uint4 hv = ((const uint4*)eh)[tid];
    uint4 lv = ((const uint4*)el)[tid];
    const ushort* hp = (const ushort*)&hv;
    const ushort* lq = (const ushort*)&lv;
    uint4 ov;
    ushort* op = (ushort*)&ov;
#pragma unroll
    for (int i = 0; i < 8; i++) {
        float v = (__bfloat162float(__ushort_as_bfloat16(hp[i])) +
                   __bfloat162float(__ushort_as_bfloat16(lq[i]))) * inv;
        op[i] = __half_as_ushort(__float2half(v));
    }
    ((uint4*)po)[tid] = ov;
}

// ---------------- BN scale/shift from fixed-point sums ----------------
__global__ void bn_stats2_kernel(const float* __restrict__ gamma,
                                 const float* __restrict__ beta,
                                 float* __restrict__ scale,
                                 float* __restrict__ shift)
{
    int c = blockIdx.x * blockDim.x + threadIdx.x;
    if (c >= C_) return;
    const double M = (double)(B_ * N_);
    double mean = (double)(long long)d_bnsum[c]  / SC1 / M;
    double ms   = (double)(long long)d_bnsum2[c] / SC2 / M;
    double var  = ms - mean * mean;
    double inv  = 1.0 / sqrt(var + 1e-5);
    double sc   = (double)gamma[c] * inv;
    scale[c] = (float)sc;
    shift[c] = (float)((double)beta[c] - mean * sc);
}

// ---------------- finalize ----------------
__global__ void finalize_kernel(const float* __restrict__ zp,
                                const float* __restrict__ x,
                                const float* __restrict__ scale,
                                const float* __restrict__ shift,
                                float* __restrict__ out)
{
    const size_t idx4 = (size_t)blockIdx.x * blockDim.x + threadIdx.x;
    const size_t total4 = (size_t)B_ * C_ * N_ / 4;
    if (idx4 >= total4) return;
    const int nq = N_ / 4;
    int n4 = (int)(idx4 % nq);
    int c  = (int)((idx4 / nq) % C_);
    int b  = (int)(idx4 / ((size_t)nq * C_));

    float4 z = ((const float4*)zp)[(size_t)c * (B_ * N_ / 4) + (size_t)b * nq + n4];
    float4 xv = ((const float4*)x)[idx4];
    const float sc = scale[c], sh = shift[c];
    float4 o;
    o.x = z.x * sc + sh + xv.x;
    o.y = z.y * sc + sh + xv.y;
    o.z = z.z * sc + sh + xv.z;
    o.w = z.w * sc + sh + xv.w;
    ((float4*)out)[idx4] = o;
}

// ---------------- launch ----------------
template <typename T>
static T* sym_addr(const void* sym)
{
    void* p = nullptr;
    cudaGetSymbolAddress(&p, sym);
    return (T*)p;
}

extern "C" void kernel_launch(void* const* d_in, const int* in_sizes, int n_in,
                              void* d_out, int out_size)
{
    const float* x     = (const float*)d_in[0];
    const float* Wg    = (const float*)d_in[1];
    const float* Wth   = (const float*)d_in[2];
    const float* Wph   = (const float*)d_in[3];
    const float* Wz    = (const float*)d_in[4];
    const float* gamma = (const float*)d_in[5];
    const float* beta  = (const float*)d_in[6];
    float* out = (float*)d_out;

    __half*  xs  = sym_addr<__half>(d_xs);
    __half*  Wtp = sym_addr<__half>(d_Wtp);
    __half*  WgS = sym_addr<__half>(d_WgS);
    __half*  WzS = sym_addr<__half>(d_WzS);
    __half*  tp  = sym_addr<__half>(d_tp);
    __half*  gS  = sym_addr<__half>(d_gS);
    __half*  OS  = sym_addr<__half>(d_OS);
    __half*  P   = sym_addr<__half>(d_P);
    __nv_bfloat16* E = sym_addr<__nv_bfloat16>(d_E);
    float*   lp  = sym_addr<float>(d_lpar);
    float* zp    = sym_addr<float>(d_zp);
    float* scale = sym_addr<float>(d_scale);
    float* shift = sym_addr<float>(d_shift);

    cudaFuncSetAttribute(gemm_mma_kernel<1, 1>,
                         cudaFuncAttributeMaxDynamicSharedMemorySize, GEMM_SMEM);
    cudaFuncSetAttribute(gemm_mma_kernel<1, 0>,
                         cudaFuncAttributeMaxDynamicSharedMemorySize, GEMM_SMEM);

    // 1) weight splits (fp16 limbs) + zero bn accumulators
    split_all_kernel<<<dim3((P_ * C_ + 255) / 256, 4), 256>>>(
        Wth, Wph, Wg, Wz, Wtp, WgS, WzS);
    // 2) x transpose + split (fp16 limbs)
    xsplit_kernel<<<dim3(N_ / 32, C_ / 32, B_), dim3(32, 32)>>>(x, xs);

    // 3) theta+phi merged (fp16 in, fp16 limbs out), 3 terms
    gemm_mma_kernel<1, 1><<<dim3((2 * P_) / 128, N_ / 128, B_), 256, GEMM_SMEM>>>(
        (const uint16_t*)xs, 2 * C_, C_, (const uint16_t*)Wtp, 2 * C_, C_,
        tp, 4 * P_, C_, 1, 2 * P_, 3, 0b100, 0b010,
        (size_t)N_ * 2 * C_, 0, (size_t)N_ * 4 * P_, nullptr);
    // 4) g^T (fp16 in, fp16 single-limb out), 1 term (hi x hi)
    gemm_mma_kernel<1, 1><<<dim3(N_ / 128, P_ / 128, B_), 256, GEMM_SMEM>>>(
        (const uint16_t*)WgS, 2 * C_, C_, (const uint16_t*)xs, 2 * C_, C_,
        gS, 2 * N_, C_, 1, 0 /*hi only*/, 1, 0, 0,
        0, (size_t)N_ * 2 * C_, (size_t)P_ * 2 * N_, nullptr);
    // 5) scores (fp16 in) -> E bf16 split + row partial sums, 3 terms
    gemm_mma_kernel<1, 0><<<dim3(N_ / 128, N_ / 128, B_), 256, GEMM_SMEM>>>(
        (const uint16_t*)tp, 4 * P_, 2 * P_, (const uint16_t*)(tp + P_), 4 * P_, 2 * P_,
        E, 2 * N_, P_, 2, N_, 3, 0b100, 0b010,
        (size_t)N_ * 4 * P_, (size_t)N_ * 4 * P_, (size_t)N_ * 2 * N_, lp);
    // 6) normalize: P = (E_hi + E_lo) / l, fp16 single limb
    normalize_kernel<<<B_ * N_, 256>>>(E, lp, P);
    // 7) PV (fp16 in): O = P x g_hi, 1 term, compact single-limb OS (ldc = P)
    gemm_mma_kernel<1, 1><<<dim3(P_ / 128, N_ / 128, B_), 256, GEMM_SMEM>>>(
        (const uint16_t*)P, N_, 0, (const uint16_t*)gS, 2 * N_, N_,
        OS, P_, N_, 1, 0 /*hi only*/, 1, 0, 0,
        (size_t)N_ * N_, (size_t)P_ * 2 * N_, (size_t)N_ * P_, nullptr);
    // 8) z (fp16 in) fp32 out + fused BN channel sums, 1 term (OS compact, ldb = P)
    gemm_mma_kernel<1, 0><<<dim3((B_ * N_) / 128, C_ / 128, 1), 256, GEMM_SMEM>>>(
        (const uint16_t*)WzS, 2 * P_, P_, (const uint16_t*)OS, P_, 0,
        zp, B_ * N_, P_, 4, 0, 1, 0, 0,
        0, 0, 0, nullptr);
    // 9) BN scale/shift
    bn_stats2_kernel<<<2, 256>>>(gamma, beta, scale, shift);
    // 10) finalize
    {
        const int total4 = B_ * C_ * N_ / 4;
        finalize_kernel<<<(total4 + 255) / 256, 256>>>(zp, x, scale, shift, out);
    }
}